// round 2
// baseline (speedup 1.0000x reference)
#include <cuda_runtime.h>
#include <math.h>
#include <stdint.h>

#define B_   256
#define S1_  512
#define S2_  64
#define H_   768
#define OPC_ 64
#define OT_  128            // OPC + S2
#define NEGV (-1e12f)

// ---------------- scratch (device globals) ----------------------------------
__device__ float g_lc  [B_ * 2 * H_];
__device__ float g_gA  [B_ * H_];
__device__ float g_gB  [B_ * H_];
__device__ float g_gC  [B_ * H_];
__device__ float g_gD  [B_ * H_];
__device__ float g_node[B_ * H_];
__device__ float g_P1  [B_ * H_];
__device__ float g_eng [B_ * S1_];
__device__ float g_ctx [B_ * H_];
__device__ float g_leaf[B_ * 2 * H_];
__device__ float g_Q1  [B_ * H_];
__device__ float g_Q2c [OPC_ * H_];

// ---------------- fast math helpers -----------------------------------------
__device__ __forceinline__ float ftanh(float x) {
    // tanh(x) = sign(x) * (1 - 2/(exp(2|x|)+1)); robust for |x| large (exp->inf -> 1)
    float ax = fabsf(x);
    float e  = __expf(2.0f * ax);
    float r  = 1.0f - __fdividef(2.0f, e + 1.0f);
    return copysignf(r, x);
}
__device__ __forceinline__ float fsig(float x) {
    return __fdividef(1.0f, 1.0f + __expf(-x));
}

// ---------------- f32x2 packed FMA primitives --------------------------------
__device__ __forceinline__ unsigned long long dup2(float a) {
    unsigned long long r;
    asm("mov.b64 %0, {%1, %1};" : "=l"(r) : "f"(a));
    return r;
}
__device__ __forceinline__ void ffma2(unsigned long long& d,
                                      unsigned long long a, unsigned long long b) {
    asm("fma.rn.f32x2 %0, %1, %2, %0;" : "+l"(d) : "l"(a), "l"(b));
}
__device__ __forceinline__ float2 unpk(unsigned long long v) {
    float2 f;
    asm("mov.b64 {%0, %1}, %2;" : "=f"(f.x), "=f"(f.y) : "l"(v));
    return f;
}

// ---------------- unified f32x2 GEMM, 128x128 tile, BK=16, 256 thr, 8x8/thr --
// MODE 0: split-K, atomicAdd C (C preloaded with bias)      grid.z = splits
// MODE 1: fused attention energy: atomicAdd_r g_eng[r] += sum_c v[c]*tanh(P1[b,c]+acc)
// MODE 2: fused leaf score:       atomicAdd out_score[b,64+s2] += sum_c v[c]*tanh(Q1[b,c]+acc)
template <int MODE>
__global__ __launch_bounds__(256) void gemm_f2_k(
    const float* __restrict__ A, const float* __restrict__ Bm,
    float* __restrict__ C,
    const float* __restrict__ aux1,   // MODE1: P1, MODE2: Q1
    const float* __restrict__ aux2,   // MODE1: v_attn, MODE2: v_score
    int M, int N, int K, int Klen)
{
    __shared__ __align__(16) float As[16][128];
    __shared__ __align__(16) float Bs[16][132];
    __shared__ float red[128][17];

    const int tid = threadIdx.x;
    const int bm = blockIdx.y * 128;
    const int bn = blockIdx.x * 128;
    const int k0 = blockIdx.z * Klen;
    const int tx = tid & 15;
    const int ty = tid >> 4;

    unsigned long long acc[8][4];
#pragma unroll
    for (int i = 0; i < 8; i++)
#pragma unroll
        for (int j = 0; j < 4; j++) acc[i][j] = 0ULL;

    const int a_row = tid >> 1;
    const int a_col = (tid & 1) * 8;
    const bool a_ok = (bm + a_row) < M;
    const float* Aptr = A + (size_t)(bm + a_row) * K + k0 + a_col;

    const int b_row = tid >> 4;
    const int b_col = (tid & 15) * 8;
    const float* Bptr = Bm + (size_t)(k0 + b_row) * N + bn + b_col;

    for (int kk = 0; kk < Klen; kk += 16) {
        float4 a0, a1;
        if (a_ok) {
            a0 = *(const float4*)(Aptr);
            a1 = *(const float4*)(Aptr + 4);
        } else {
            a0 = make_float4(0.f, 0.f, 0.f, 0.f);
            a1 = a0;
        }
        float4 b0 = *(const float4*)(Bptr);
        float4 b1 = *(const float4*)(Bptr + 4);

        As[a_col + 0][a_row] = a0.x;
        As[a_col + 1][a_row] = a0.y;
        As[a_col + 2][a_row] = a0.z;
        As[a_col + 3][a_row] = a0.w;
        As[a_col + 4][a_row] = a1.x;
        As[a_col + 5][a_row] = a1.y;
        As[a_col + 6][a_row] = a1.z;
        As[a_col + 7][a_row] = a1.w;
        *(float4*)&Bs[b_row][b_col]     = b0;
        *(float4*)&Bs[b_row][b_col + 4] = b1;
        __syncthreads();

#pragma unroll
        for (int k = 0; k < 16; k++) {
            float a[8];
            *(float4*)(a)     = *(const float4*)&As[k][ty * 8];
            *(float4*)(a + 4) = *(const float4*)&As[k][ty * 8 + 4];
            ulonglong2 bb01 = *(const ulonglong2*)&Bs[k][tx * 8];
            ulonglong2 bb23 = *(const ulonglong2*)&Bs[k][tx * 8 + 4];
            unsigned long long bb[4] = {bb01.x, bb01.y, bb23.x, bb23.y};
#pragma unroll
            for (int i = 0; i < 8; i++) {
                unsigned long long aa = dup2(a[i]);
#pragma unroll
                for (int j = 0; j < 4; j++) ffma2(acc[i][j], aa, bb[j]);
            }
        }
        __syncthreads();

        Aptr += 16;
        Bptr += (size_t)16 * N;
    }

    if (MODE == 0) {
#pragma unroll
        for (int i = 0; i < 8; i++) {
            int r = bm + ty * 8 + i;
            if (r < M) {
                float* Cr = C + (size_t)r * N + bn + tx * 8;
#pragma unroll
                for (int j = 0; j < 4; j++) {
                    float2 p = unpk(acc[i][j]);
                    atomicAdd(Cr + 2 * j,     p.x);
                    atomicAdd(Cr + 2 * j + 1, p.y);
                }
            }
        }
    } else if (MODE == 1) {
        // all 128 rows of this block belong to batch b (S1=512 is a multiple of 128)
        const int b = bm >> 9;              // bm / S1_
        float pv[8], vv[8];
#pragma unroll
        for (int jj = 0; jj < 8; jj++) {
            int c = bn + tx * 8 + jj;
            pv[jj] = __ldg(&aux1[(size_t)b * H_ + c]);
            vv[jj] = __ldg(&aux2[c]);
        }
#pragma unroll
        for (int i = 0; i < 8; i++) {
            float part = 0.f;
#pragma unroll
            for (int j = 0; j < 4; j++) {
                float2 p = unpk(acc[i][j]);
                part += vv[2 * j]     * ftanh(pv[2 * j]     + p.x);
                part += vv[2 * j + 1] * ftanh(pv[2 * j + 1] + p.y);
            }
            red[ty * 8 + i][tx] = part;
        }
        __syncthreads();
        if (tid < 128) {
            float s = 0.f;
#pragma unroll
            for (int t = 0; t < 16; t++) s += red[tid][t];
            atomicAdd(&C[bm + tid], s);
        }
    } else {  // MODE == 2: leaf score over var_pades rows (r = b*64 + s2)
        float vv[8];
#pragma unroll
        for (int jj = 0; jj < 8; jj++) vv[jj] = __ldg(&aux2[bn + tx * 8 + jj]);
#pragma unroll
        for (int i = 0; i < 8; i++) {
            int r = bm + ty * 8 + i;
            const float* q1 = aux1 + (size_t)(r >> 6) * H_;
            float part = 0.f;
#pragma unroll
            for (int j = 0; j < 4; j++) {
                float2 p = unpk(acc[i][j]);
                int c = bn + tx * 8 + 2 * j;
                part += vv[2 * j]     * ftanh(__ldg(&q1[c])     + p.x);
                part += vv[2 * j + 1] * ftanh(__ldg(&q1[c + 1]) + p.y);
            }
            red[ty * 8 + i][tx] = part;
        }
        __syncthreads();
        if (tid < 128) {
            int r = bm + tid;
            float s = 0.f;
#pragma unroll
            for (int t = 0; t < 16; t++) s += red[r - bm][t];
            atomicAdd(&C[(size_t)(r >> 6) * OT_ + OPC_ + (r & 63)], s);
        }
    }
}

// ---------------- small helper kernels ---------------------------------------
__global__ void fill_k(float* __restrict__ C, const float* __restrict__ bias,
                       int total, int N)
{
    int i = blockIdx.x * blockDim.x + threadIdx.x;
    if (i < total) C[i] = bias ? bias[i % N] : 0.f;
}

__global__ void concat2_k(const float* __restrict__ x, const float* __restrict__ y,
                          float* __restrict__ out)
{
    int i = blockIdx.x * blockDim.x + threadIdx.x;
    if (i >= B_ * H_) return;
    int b = i / H_, h = i % H_;
    out[(size_t)b * 2 * H_ + h]      = x[i];
    out[(size_t)b * 2 * H_ + H_ + h] = y[i];
}

__global__ void combine_node_k(const int* __restrict__ has_left)
{
    int i = blockIdx.x * blockDim.x + threadIdx.x;
    if (i >= B_ * H_) return;
    int b = i / H_;
    float v;
    if (has_left[b])
        v = ftanh(g_gC[i]) * fsig(g_gD[i]);
    else
        v = ftanh(g_gA[i]) * fsig(g_gB[i]);
    g_node[i] = v;
}

// softmax over S1 per batch (mask applied here on the raw accumulated energies)
__global__ void softmax_k(const int* __restrict__ smask)
{
    __shared__ float red[256];
    int b = blockIdx.x, t = threadIdx.x;
    float* e = g_eng + (size_t)b * S1_;
    const int* m = smask + (size_t)b * S1_;
    float x0 = m[t]       ? NEGV : e[t];
    float x1 = m[t + 256] ? NEGV : e[t + 256];
    red[t] = fmaxf(x0, x1);
    __syncthreads();
    for (int s = 128; s > 0; s >>= 1) {
        if (t < s) red[t] = fmaxf(red[t], red[t + s]);
        __syncthreads();
    }
    float mx = red[0];
    __syncthreads();
    float e0 = __expf(x0 - mx), e1 = __expf(x1 - mx);
    red[t] = e0 + e1;
    __syncthreads();
    for (int s = 128; s > 0; s >>= 1) {
        if (t < s) red[t] += red[t + s];
        __syncthreads();
    }
    float inv = __fdividef(1.f, red[0]);
    e[t]       = e0 * inv;
    e[t + 256] = e1 * inv;
}

__global__ void context_k(const float* __restrict__ enc)
{
    int b = blockIdx.x, h = threadIdx.x;
    const float* a = g_eng + (size_t)b * S1_;
    const float* e = enc + (size_t)b * S1_ * H_ + h;
    float acc = 0.f;
#pragma unroll 8
    for (int s = 0; s < S1_; s++)
        acc = fmaf(__ldg(a + s), __ldg(e + (size_t)s * H_), acc);
    g_ctx[(size_t)b * H_ + h] = acc;
}

// o < OPC: compute full score from Q2c; all o: apply candidate mask
__global__ void finalize_score_k(const float* __restrict__ vsc,
                                 const int* __restrict__ cmask,
                                 float* __restrict__ score)
{
    int idx = (blockIdx.x * blockDim.x + threadIdx.x) >> 5;
    if (idx >= B_ * OT_) return;
    int lane = threadIdx.x & 31;
    int b = idx >> 7, o = idx & 127;
    if (cmask[idx]) {
        if (lane == 0) score[idx] = NEGV;
        return;
    }
    if (o >= OPC_) return;   // var part already accumulated by fused GEMM
    const float* q1 = g_Q1 + (size_t)b * H_;
    const float* q2 = g_Q2c + (size_t)o * H_;
    float acc = 0.f;
    for (int h = lane; h < H_; h += 32)
        acc += vsc[h] * ftanh(q1[h] + q2[h]);
#pragma unroll
    for (int off = 16; off; off >>= 1) acc += __shfl_xor_sync(0xFFFFFFFFu, acc, off);
    if (lane == 0) score[idx] = acc;
}

__global__ void copy_k(const float* __restrict__ src, float* __restrict__ dst, int n)
{
    int i = blockIdx.x * blockDim.x + threadIdx.x;
    if (i < n) dst[i] = src[i];
}

__global__ void emb_all_k(const float* __restrict__ opc, const float* __restrict__ var,
                          float* __restrict__ dst)
{
    size_t i = (size_t)blockIdx.x * blockDim.x + threadIdx.x;
    const size_t total = (size_t)B_ * OT_ * H_ / 4;
    if (i >= total) return;
    size_t elem = i * 4;
    int h = (int)(elem % H_);
    size_t bo = elem / H_;
    int o = (int)(bo % OT_);
    int b = (int)(bo / OT_);
    float4 v;
    if (o < OPC_)
        v = *(const float4*)(opc + (size_t)o * H_ + h);
    else
        v = *(const float4*)(var + ((size_t)b * S2_ + (o - OPC_)) * H_ + h);
    ((float4*)dst)[i] = v;
}

// ---------------- launch ------------------------------------------------------
static inline void gemm_split(const float* A, const float* B, float* C,
                              int M, int N, int K, int splits)
{
    dim3 grid(N / 128, (M + 127) / 128, splits);
    gemm_f2_k<0><<<grid, 256>>>(A, B, C, nullptr, nullptr, M, N, K, K / splits);
}

extern "C" void kernel_launch(void* const* d_in, const int* in_sizes, int n_in,
                              void* d_out, int out_size)
{
    (void)in_sizes; (void)n_in; (void)out_size;
    const float* current = (const float*)d_in[0];
    const float* left    = (const float*)d_in[1];
    const float* enc     = (const float*)d_in[2];
    const float* var     = (const float*)d_in[3];
    const float* opc     = (const float*)d_in[4];
    const float* W_l     = (const float*)d_in[5];
    const float* b_l     = (const float*)d_in[6];
    const float* W_lg    = (const float*)d_in[7];
    const float* b_lg    = (const float*)d_in[8];
    const float* W_r     = (const float*)d_in[9];
    const float* b_r     = (const float*)d_in[10];
    const float* W_rg    = (const float*)d_in[11];
    const float* b_rg    = (const float*)d_in[12];
    const float* W_attn  = (const float*)d_in[13];
    const float* b_attn  = (const float*)d_in[14];
    const float* v_attn  = (const float*)d_in[15];
    const float* W_score = (const float*)d_in[16];
    const float* b_score = (const float*)d_in[17];
    const float* v_score = (const float*)d_in[18];
    const int*   has_left = (const int*)d_in[19];
    const int*   smask    = (const int*)d_in[20];
    const int*   cmask    = (const int*)d_in[21];

    float *lc, *gA, *gB, *gC, *gD, *node, *P1, *eng, *ctx, *leaf, *Q1, *Q2c;
    cudaGetSymbolAddress((void**)&lc,   g_lc);
    cudaGetSymbolAddress((void**)&gA,   g_gA);
    cudaGetSymbolAddress((void**)&gB,   g_gB);
    cudaGetSymbolAddress((void**)&gC,   g_gC);
    cudaGetSymbolAddress((void**)&gD,   g_gD);
    cudaGetSymbolAddress((void**)&node, g_node);
    cudaGetSymbolAddress((void**)&P1,   g_P1);
    cudaGetSymbolAddress((void**)&eng,  g_eng);
    cudaGetSymbolAddress((void**)&ctx,  g_ctx);
    cudaGetSymbolAddress((void**)&leaf, g_leaf);
    cudaGetSymbolAddress((void**)&Q1,   g_Q1);
    cudaGetSymbolAddress((void**)&Q2c,  g_Q2c);

    float* out       = (float*)d_out;
    float* out_score = out;                      // [B, 128]
    float* out_node  = out_score + B_ * OT_;     // [B, 1, H]
    float* out_ctx   = out_node + B_ * H_;       // [B, 1, H]
    float* out_emb   = out_ctx + B_ * H_;        // [B, 128, H]

    const int BH = B_ * H_;
    const int TPB = 256;

    // --- node: four gate GEMMs (split-K, bias preloaded) ---
    concat2_k<<<(BH + TPB - 1) / TPB, TPB>>>(left, current, lc);
    fill_k<<<(BH + TPB - 1) / TPB, TPB>>>(gA, b_l,  BH, H_);
    fill_k<<<(BH + TPB - 1) / TPB, TPB>>>(gB, b_lg, BH, H_);
    fill_k<<<(BH + TPB - 1) / TPB, TPB>>>(gC, b_r,  BH, H_);
    fill_k<<<(BH + TPB - 1) / TPB, TPB>>>(gD, b_rg, BH, H_);
    gemm_split(current, W_l,  gA, B_, H_, H_,     6);
    gemm_split(current, W_lg, gB, B_, H_, H_,     6);
    gemm_split(lc,      W_r,  gC, B_, H_, 2 * H_, 12);
    gemm_split(lc,      W_rg, gD, B_, H_, 2 * H_, 12);
    combine_node_k<<<(BH + TPB - 1) / TPB, TPB>>>(has_left);

    // --- attention: P1 = node@W1 + b_attn; fused (enc@W2 -> energy) ---
    fill_k<<<(BH + TPB - 1) / TPB, TPB>>>(P1, b_attn, BH, H_);
    gemm_split(node, W_attn, P1, B_, H_, H_, 6);
    fill_k<<<(B_ * S1_ + TPB - 1) / TPB, TPB>>>(eng, nullptr, B_ * S1_, 1);
    {
        dim3 grid(H_ / 128, (B_ * S1_) / 128, 1);
        gemm_f2_k<1><<<grid, 256>>>(enc, W_attn + (size_t)H_ * H_, eng,
                                    P1, v_attn, B_ * S1_, H_, H_, H_);
    }
    softmax_k<<<B_, 256>>>(smask);
    context_k<<<B_, H_>>>(enc);

    // --- leaf score ---
    concat2_k<<<(BH + TPB - 1) / TPB, TPB>>>(node, ctx, leaf);
    fill_k<<<(BH + TPB - 1) / TPB, TPB>>>(Q1, b_score, BH, H_);
    gemm_split(leaf, W_score, Q1, B_, H_, 2 * H_, 12);
    fill_k<<<(OPC_ * H_ + TPB - 1) / TPB, TPB>>>(Q2c, nullptr, OPC_ * H_, 1);
    gemm_split(opc, W_score + (size_t)2 * H_ * H_, Q2c, OPC_, H_, H_, 6);
    fill_k<<<(B_ * OT_ + TPB - 1) / TPB, TPB>>>(out_score, nullptr, B_ * OT_, 1);
    {
        dim3 grid(H_ / 128, (B_ * S2_) / 128, 1);
        gemm_f2_k<2><<<grid, 256>>>(var, W_score + (size_t)2 * H_ * H_, out_score,
                                    Q1, v_score, B_ * S2_, H_, H_, H_);
    }
    finalize_score_k<<<(B_ * OT_ * 32 + TPB - 1) / TPB, TPB>>>(v_score, cmask, out_score);

    // --- remaining outputs ---
    copy_k<<<(BH + TPB - 1) / TPB, TPB>>>(node, out_node, BH);
    copy_k<<<(BH + TPB - 1) / TPB, TPB>>>(ctx,  out_ctx,  BH);
    {
        size_t total4 = (size_t)B_ * OT_ * H_ / 4;
        emb_all_k<<<(unsigned)((total4 + TPB - 1) / TPB), TPB>>>(opc, var, out_emb);
    }
}

// round 4
// speedup vs baseline: 2.4732x; 2.4732x over previous
#include <cuda_runtime.h>
#include <math.h>
#include <stdint.h>

#define B_   256
#define S1_  512
#define S2_  64
#define H_   768
#define OPC_ 64
#define OT_  128
#define NEGV (-1e12f)

// ---------------- scratch (device globals) ----------------------------------
__device__ float g_lc  [B_ * 2 * H_];
__device__ float g_gA  [B_ * H_];
__device__ float g_gB  [B_ * H_];
__device__ float g_gC  [B_ * H_];
__device__ float g_gD  [B_ * H_];
__device__ float g_node[B_ * H_];
__device__ float g_P1  [B_ * H_];
__device__ float g_eng [B_ * S1_];
__device__ float g_ctx [B_ * H_];
__device__ float g_leaf[B_ * 2 * H_];
__device__ float g_Q1  [B_ * H_];
__device__ float g_Q2c [OPC_ * H_];
__device__ float g_WtA [H_ * H_];     // transpose of W_attn[H:2H]
__device__ float g_WtS [H_ * H_];     // transpose of W_score[2H:3H]

// ---------------- helpers ------------------------------------------------------
__device__ __forceinline__ float tanh_fast(float x) {
    float y; asm("tanh.approx.f32 %0, %1;" : "=f"(y) : "f"(x)); return y;
}
__device__ __forceinline__ float ftanh(float x) {
    float ax = fabsf(x);
    float e  = __expf(2.0f * ax);
    float r  = 1.0f - __fdividef(2.0f, e + 1.0f);
    return copysignf(r, x);
}
__device__ __forceinline__ float fsig(float x) {
    return __fdividef(1.0f, 1.0f + __expf(-x));
}
__device__ __forceinline__ uint32_t to_tf32(float x) {
    uint32_t r; asm("cvt.rna.tf32.f32 %0, %1;" : "=r"(r) : "f"(x)); return r;
}
__device__ __forceinline__ void mma_tf32(float c[4], const uint32_t a[4],
                                         const uint32_t b[2]) {
    asm volatile(
        "mma.sync.aligned.m16n8k8.row.col.f32.tf32.tf32.f32 "
        "{%0,%1,%2,%3}, {%4,%5,%6,%7}, {%8,%9}, {%0,%1,%2,%3};"
        : "+f"(c[0]), "+f"(c[1]), "+f"(c[2]), "+f"(c[3])
        : "r"(a[0]), "r"(a[1]), "r"(a[2]), "r"(a[3]), "r"(b[0]), "r"(b[1]));
}

// ---------------- fused big GEMM via warp-mma tf32 ----------------------------
// C-tile 128m x 128n, BK=16, 256 threads = 8 warps (4 m-bands x 2 n-halves),
// warp tile 32x64 = 2 x 8 (m16n8k8). K = 768 fixed. A row-major [M,768],
// Wt row-major [N=768? no: N rows][768] (Wt[n][k] = W[k][n]).
// MODE 1: energy out[r] += sum_n v[n]*tanh(P1[b,n]+acc), b = bm>>9
// MODE 2: score  out[(r>>6)*128 + 64 + (r&63)] += sum_n v[n]*tanh(Q1[r>>6,n]+acc)
template <int MODE>
__global__ __launch_bounds__(256) void mma_fused_k(
    const float* __restrict__ A, const float* __restrict__ Wt,
    float* __restrict__ outv,
    const float* __restrict__ aux1, const float* __restrict__ aux2)
{
    __shared__ uint32_t As[16][132];
    __shared__ uint32_t Bs[16][132];

    const int tid  = threadIdx.x;
    const int wid  = tid >> 5;
    const int lane = tid & 31;
    const int wm   = wid & 3;          // m-band (32 rows)
    const int wn   = wid >> 2;         // n-half (64 cols)
    const int bm   = blockIdx.y * 128;
    const int bn   = blockIdx.x * 128;

    float acc[2][8][4];
#pragma unroll
    for (int i = 0; i < 2; i++)
#pragma unroll
        for (int j = 0; j < 8; j++)
#pragma unroll
            for (int q = 0; q < 4; q++) acc[i][j][q] = 0.f;

    // A loader: thread -> row tid>>1, k cols (tid&1)*8 .. +7
    const int a_row = tid >> 1;
    const int a_col = (tid & 1) * 8;
    const float* Ap = A + (size_t)(bm + a_row) * H_ + a_col;
    // B loader: thread -> n col tid&127, k quads at (tid>>7)*4 and +8
    const int b_n  = tid & 127;
    const int b_kq = (tid >> 7) * 4;
    const float* Bp = Wt + (size_t)(bn + b_n) * H_ + b_kq;

    const int lk = lane & 3;           // k offset within frag
    const int lg = lane >> 2;          // group id (row/col within frag)

    for (int k0 = 0; k0 < H_; k0 += 16) {
        float4 a0 = *(const float4*)Ap;
        float4 a1 = *(const float4*)(Ap + 4);
        float4 q0 = *(const float4*)Bp;
        float4 q1 = *(const float4*)(Bp + 8);

        As[a_col + 0][a_row] = to_tf32(a0.x);
        As[a_col + 1][a_row] = to_tf32(a0.y);
        As[a_col + 2][a_row] = to_tf32(a0.z);
        As[a_col + 3][a_row] = to_tf32(a0.w);
        As[a_col + 4][a_row] = to_tf32(a1.x);
        As[a_col + 5][a_row] = to_tf32(a1.y);
        As[a_col + 6][a_row] = to_tf32(a1.z);
        As[a_col + 7][a_row] = to_tf32(a1.w);
        Bs[b_kq + 0][b_n] = to_tf32(q0.x);
        Bs[b_kq + 1][b_n] = to_tf32(q0.y);
        Bs[b_kq + 2][b_n] = to_tf32(q0.z);
        Bs[b_kq + 3][b_n] = to_tf32(q0.w);
        Bs[b_kq + 8][b_n]  = to_tf32(q1.x);
        Bs[b_kq + 9][b_n]  = to_tf32(q1.y);
        Bs[b_kq + 10][b_n] = to_tf32(q1.z);
        Bs[b_kq + 11][b_n] = to_tf32(q1.w);
        __syncthreads();

#pragma unroll
        for (int kk = 0; kk < 16; kk += 8) {
            uint32_t af[2][4], bf[8][2];
#pragma unroll
            for (int ti = 0; ti < 2; ti++) {
                int m = wm * 32 + ti * 16 + lg;
                af[ti][0] = As[kk + lk][m];
                af[ti][1] = As[kk + lk][m + 8];
                af[ti][2] = As[kk + 4 + lk][m];
                af[ti][3] = As[kk + 4 + lk][m + 8];
            }
#pragma unroll
            for (int nj = 0; nj < 8; nj++) {
                int n = wn * 64 + nj * 8 + lg;
                bf[nj][0] = Bs[kk + lk][n];
                bf[nj][1] = Bs[kk + 4 + lk][n];
            }
#pragma unroll
            for (int ti = 0; ti < 2; ti++)
#pragma unroll
                for (int nj = 0; nj < 8; nj++)
                    mma_tf32(acc[ti][nj], af[ti], bf[nj]);
        }
        __syncthreads();

        Ap += 16;
        Bp += 16;
    }

    // ---------------- fused epilogue ----------------
    float vv[16];
#pragma unroll
    for (int nj = 0; nj < 8; nj++)
#pragma unroll
        for (int u = 0; u < 2; u++)
            vv[nj * 2 + u] = __ldg(&aux2[bn + wn * 64 + nj * 8 + 2 * lk + u]);

    if (MODE == 1) {
        const int b = bm >> 9;
        float p1v[16];
#pragma unroll
        for (int nj = 0; nj < 8; nj++)
#pragma unroll
            for (int u = 0; u < 2; u++)
                p1v[nj * 2 + u] = __ldg(&aux1[(size_t)b * H_ + bn + wn * 64 + nj * 8 + 2 * lk + u]);
#pragma unroll
        for (int ti = 0; ti < 2; ti++)
#pragma unroll
            for (int half = 0; half < 2; half++) {
                int r = bm + wm * 32 + ti * 16 + lg + half * 8;
                float part = 0.f;
#pragma unroll
                for (int nj = 0; nj < 8; nj++) {
                    part += vv[nj * 2]     * tanh_fast(acc[ti][nj][half * 2]     + p1v[nj * 2]);
                    part += vv[nj * 2 + 1] * tanh_fast(acc[ti][nj][half * 2 + 1] + p1v[nj * 2 + 1]);
                }
                part += __shfl_xor_sync(0xFFFFFFFFu, part, 1);
                part += __shfl_xor_sync(0xFFFFFFFFu, part, 2);
                if (lk == 0) atomicAdd(&outv[r], part);
            }
    } else {
#pragma unroll
        for (int ti = 0; ti < 2; ti++)
#pragma unroll
            for (int half = 0; half < 2; half++) {
                int r = bm + wm * 32 + ti * 16 + lg + half * 8;
                int b = r >> 6;
                const float* q1 = aux1 + (size_t)b * H_;
                float part = 0.f;
#pragma unroll
                for (int nj = 0; nj < 8; nj++) {
                    int n = bn + wn * 64 + nj * 8 + 2 * lk;
                    part += vv[nj * 2]     * tanh_fast(acc[ti][nj][half * 2]     + __ldg(&q1[n]));
                    part += vv[nj * 2 + 1] * tanh_fast(acc[ti][nj][half * 2 + 1] + __ldg(&q1[n + 1]));
                }
                part += __shfl_xor_sync(0xFFFFFFFFu, part, 1);
                part += __shfl_xor_sync(0xFFFFFFFFu, part, 2);
                if (lk == 0) atomicAdd(&outv[(size_t)b * OT_ + OPC_ + (r & 63)], part);
            }
    }
}

// ---------------- scalar-FFMA split-K SGEMM (small GEMMs) --------------------
__global__ __launch_bounds__(256) void sgemm_atomic_k(
    const float* __restrict__ A, const float* __restrict__ Bm,
    float* __restrict__ C, int M, int N, int K, int Klen)
{
    __shared__ float As[16][128];
    __shared__ float Bs[16][132];

    const int tid = threadIdx.x;
    const int bm = blockIdx.y * 128;
    const int bn = blockIdx.x * 128;
    const int k0 = blockIdx.z * Klen;
    const int tx = tid & 15;
    const int ty = tid >> 4;

    float acc[8][8];
#pragma unroll
    for (int i = 0; i < 8; i++)
#pragma unroll
        for (int j = 0; j < 8; j++) acc[i][j] = 0.f;

    const int a_row = tid >> 1;
    const int a_col = (tid & 1) * 8;
    const bool a_ok = (bm + a_row) < M;
    const float* Aptr = A + (size_t)(bm + a_row) * K + k0 + a_col;
    const int b_row = tid >> 4;
    const int b_col = (tid & 15) * 8;
    const float* Bptr = Bm + (size_t)(k0 + b_row) * N + bn + b_col;

    for (int kk = 0; kk < Klen; kk += 16) {
        float4 a0, a1;
        if (a_ok) { a0 = *(const float4*)Aptr; a1 = *(const float4*)(Aptr + 4); }
        else { a0 = make_float4(0.f, 0.f, 0.f, 0.f); a1 = a0; }
        float4 b0 = *(const float4*)Bptr;
        float4 b1 = *(const float4*)(Bptr + 4);

        As[a_col + 0][a_row] = a0.x; As[a_col + 1][a_row] = a0.y;
        As[a_col + 2][a_row] = a0.z; As[a_col + 3][a_row] = a0.w;
        As[a_col + 4][a_row] = a1.x; As[a_col + 5][a_row] = a1.y;
        As[a_col + 6][a_row] = a1.z; As[a_col + 7][a_row] = a1.w;
        *(float4*)&Bs[b_row][b_col]     = b0;
        *(float4*)&Bs[b_row][b_col + 4] = b1;
        __syncthreads();

#pragma unroll
        for (int k = 0; k < 16; k++) {
            float a[8], b[8];
            *(float4*)(a)     = *(const float4*)&As[k][ty * 8];
            *(float4*)(a + 4) = *(const float4*)&As[k][ty * 8 + 4];
            *(float4*)(b)     = *(const float4*)&Bs[k][tx * 8];
            *(float4*)(b + 4) = *(const float4*)&Bs[k][tx * 8 + 4];
#pragma unroll
            for (int i = 0; i < 8; i++)
#pragma unroll
                for (int j = 0; j < 8; j++)
                    acc[i][j] = fmaf(a[i], b[j], acc[i][j]);
        }
        __syncthreads();
        Aptr += 16;
        Bptr += (size_t)16 * N;
    }

#pragma unroll
    for (int i = 0; i < 8; i++) {
        int r = bm + ty * 8 + i;
        if (r < M) {
            float* Cr = C + (size_t)r * N + bn + tx * 8;
#pragma unroll
            for (int j = 0; j < 8; j++) atomicAdd(Cr + j, acc[i][j]);
        }
    }
}

// ---------------- small helpers ----------------------------------------------
__global__ void fill_k(float* __restrict__ C, const float* __restrict__ bias,
                       int total, int N)
{
    int i = blockIdx.x * blockDim.x + threadIdx.x;
    if (i < total) C[i] = bias ? bias[i % N] : 0.f;
}

__global__ void transpose768_k(const float* __restrict__ src, float* __restrict__ dst)
{
    __shared__ float t[32][33];
    int bx = blockIdx.x * 32, by = blockIdx.y * 32;
    int x = threadIdx.x, y = threadIdx.y;
#pragma unroll
    for (int i = 0; i < 32; i += 8)
        t[y + i][x] = src[(size_t)(by + y + i) * H_ + bx + x];
    __syncthreads();
#pragma unroll
    for (int i = 0; i < 32; i += 8)
        dst[(size_t)(bx + y + i) * H_ + by + x] = t[x][y + i];
}

__global__ void concat2_k(const float* __restrict__ x, const float* __restrict__ y,
                          float* __restrict__ out)
{
    int i = blockIdx.x * blockDim.x + threadIdx.x;
    if (i >= B_ * H_) return;
    int b = i / H_, h = i % H_;
    out[(size_t)b * 2 * H_ + h]      = x[i];
    out[(size_t)b * 2 * H_ + H_ + h] = y[i];
}

__global__ void combine_node_k(const int* __restrict__ has_left)
{
    int i = blockIdx.x * blockDim.x + threadIdx.x;
    if (i >= B_ * H_) return;
    int b = i / H_;
    float v = has_left[b] ? ftanh(g_gC[i]) * fsig(g_gD[i])
                          : ftanh(g_gA[i]) * fsig(g_gB[i]);
    g_node[i] = v;
}

__global__ void softmax_k(const int* __restrict__ smask)
{
    __shared__ float red[256];
    int b = blockIdx.x, t = threadIdx.x;
    float* e = g_eng + (size_t)b * S1_;
    const int* m = smask + (size_t)b * S1_;
    float x0 = m[t]       ? NEGV : e[t];
    float x1 = m[t + 256] ? NEGV : e[t + 256];
    red[t] = fmaxf(x0, x1);
    __syncthreads();
    for (int s = 128; s > 0; s >>= 1) {
        if (t < s) red[t] = fmaxf(red[t], red[t + s]);
        __syncthreads();
    }
    float mx = red[0];
    __syncthreads();
    float e0 = __expf(x0 - mx), e1 = __expf(x1 - mx);
    red[t] = e0 + e1;
    __syncthreads();
    for (int s = 128; s > 0; s >>= 1) {
        if (t < s) red[t] += red[t + s];
        __syncthreads();
    }
    float inv = __fdividef(1.f, red[0]);
    e[t] = e0 * inv;
    e[t + 256] = e1 * inv;
}

__global__ void context_k(const float* __restrict__ enc)
{
    int b = blockIdx.x, h = threadIdx.x;
    const float* a = g_eng + (size_t)b * S1_;
    const float* e = enc + (size_t)b * S1_ * H_ + h;
    float acc = 0.f;
#pragma unroll 8
    for (int s = 0; s < S1_; s++)
        acc = fmaf(__ldg(a + s), __ldg(e + (size_t)s * H_), acc);
    g_ctx[(size_t)b * H_ + h] = acc;
}

__global__ void finalize_score_k(const float* __restrict__ vsc,
                                 const int* __restrict__ cmask,
                                 float* __restrict__ score)
{
    int idx = (blockIdx.x * blockDim.x + threadIdx.x) >> 5;
    if (idx >= B_ * OT_) return;
    int lane = threadIdx.x & 31;
    int b = idx >> 7, o = idx & 127;
    if (cmask[idx]) {
        if (lane == 0) score[idx] = NEGV;
        return;
    }
    if (o >= OPC_) return;
    const float* q1 = g_Q1 + (size_t)b * H_;
    const float* q2 = g_Q2c + (size_t)o * H_;
    float acc = 0.f;
    for (int h = lane; h < H_; h += 32)
        acc += vsc[h] * ftanh(q1[h] + q2[h]);
#pragma unroll
    for (int off = 16; off; off >>= 1) acc += __shfl_xor_sync(0xFFFFFFFFu, acc, off);
    if (lane == 0) score[idx] = acc;
}

__global__ void copy_k(const float* __restrict__ src, float* __restrict__ dst, int n)
{
    int i = blockIdx.x * blockDim.x + threadIdx.x;
    if (i < n) dst[i] = src[i];
}

__global__ void emb_all_k(const float* __restrict__ opc, const float* __restrict__ var,
                          float* __restrict__ dst)
{
    size_t i = (size_t)blockIdx.x * blockDim.x + threadIdx.x;
    const size_t total = (size_t)B_ * OT_ * H_ / 4;
    if (i >= total) return;
    size_t elem = i * 4;
    int h = (int)(elem % H_);
    size_t bo = elem / H_;
    int o = (int)(bo % OT_);
    int b = (int)(bo / OT_);
    float4 v;
    if (o < OPC_) v = *(const float4*)(opc + (size_t)o * H_ + h);
    else          v = *(const float4*)(var + ((size_t)b * S2_ + (o - OPC_)) * H_ + h);
    ((float4*)dst)[i] = v;
}

// ---------------- launch -------------------------------------------------------
static inline void gemm_split(const float* A, const float* B, float* C,
                              int M, int N, int K, int splits)
{
    dim3 grid(N / 128, (M + 127) / 128, splits);
    sgemm_atomic_k<<<grid, 256>>>(A, B, C, M, N, K, K / splits);
}

extern "C" void kernel_launch(void* const* d_in, const int* in_sizes, int n_in,
                              void* d_out, int out_size)
{
    (void)in_sizes; (void)n_in; (void)out_size;
    const float* current = (const float*)d_in[0];
    const float* left    = (const float*)d_in[1];
    const float* enc     = (const float*)d_in[2];
    const float* var     = (const float*)d_in[3];
    const float* opc     = (const float*)d_in[4];
    const float* W_l     = (const float*)d_in[5];
    const float* b_l     = (const float*)d_in[6];
    const float* W_lg    = (const float*)d_in[7];
    const float* b_lg    = (const float*)d_in[8];
    const float* W_r     = (const float*)d_in[9];
    const float* b_r     = (const float*)d_in[10];
    const float* W_rg    = (const float*)d_in[11];
    const float* b_rg    = (const float*)d_in[12];
    const float* W_attn  = (const float*)d_in[13];
    const float* b_attn  = (const float*)d_in[14];
    const float* v_attn  = (const float*)d_in[15];
    const float* W_score = (const float*)d_in[16];
    const float* b_score = (const float*)d_in[17];
    const float* v_score = (const float*)d_in[18];
    const int*   has_left = (const int*)d_in[19];
    const int*   smask    = (const int*)d_in[20];
    const int*   cmask    = (const int*)d_in[21];

    float *lc, *gA, *gB, *gC, *gD, *node, *P1, *eng, *ctx, *leaf, *Q1, *Q2c, *WtA, *WtS;
    cudaGetSymbolAddress((void**)&lc,   g_lc);
    cudaGetSymbolAddress((void**)&gA,   g_gA);
    cudaGetSymbolAddress((void**)&gB,   g_gB);
    cudaGetSymbolAddress((void**)&gC,   g_gC);
    cudaGetSymbolAddress((void**)&gD,   g_gD);
    cudaGetSymbolAddress((void**)&node, g_node);
    cudaGetSymbolAddress((void**)&P1,   g_P1);
    cudaGetSymbolAddress((void**)&eng,  g_eng);
    cudaGetSymbolAddress((void**)&ctx,  g_ctx);
    cudaGetSymbolAddress((void**)&leaf, g_leaf);
    cudaGetSymbolAddress((void**)&Q1,   g_Q1);
    cudaGetSymbolAddress((void**)&Q2c,  g_Q2c);
    cudaGetSymbolAddress((void**)&WtA,  g_WtA);
    cudaGetSymbolAddress((void**)&WtS,  g_WtS);

    float* out       = (float*)d_out;
    float* out_score = out;
    float* out_node  = out_score + B_ * OT_;
    float* out_ctx   = out_node + B_ * H_;
    float* out_emb   = out_ctx + B_ * H_;

    const int BH = B_ * H_;
    const int TPB = 256;

    // --- weight transposes (independent of everything else) ---
    {
        dim3 g(24, 24), b(32, 8);
        transpose768_k<<<g, b>>>(W_attn + (size_t)H_ * H_, WtA);
        transpose768_k<<<g, b>>>(W_score + (size_t)2 * H_ * H_, WtS);
    }

    // --- node: four gate GEMMs (split-K, bias preloaded) ---
    concat2_k<<<(BH + TPB - 1) / TPB, TPB>>>(left, current, lc);
    fill_k<<<(BH + TPB - 1) / TPB, TPB>>>(gA, b_l,  BH, H_);
    fill_k<<<(BH + TPB - 1) / TPB, TPB>>>(gB, b_lg, BH, H_);
    fill_k<<<(BH + TPB - 1) / TPB, TPB>>>(gC, b_r,  BH, H_);
    fill_k<<<(BH + TPB - 1) / TPB, TPB>>>(gD, b_rg, BH, H_);
    gemm_split(current, W_l,  gA, B_, H_, H_,     6);
    gemm_split(current, W_lg, gB, B_, H_, H_,     6);
    gemm_split(lc,      W_r,  gC, B_, H_, 2 * H_, 12);
    gemm_split(lc,      W_rg, gD, B_, H_, 2 * H_, 12);
    combine_node_k<<<(BH + TPB - 1) / TPB, TPB>>>(has_left);

    // --- attention ---
    fill_k<<<(BH + TPB - 1) / TPB, TPB>>>(P1, b_attn, BH, H_);
    gemm_split(node, W_attn, P1, B_, H_, H_, 6);
    fill_k<<<(B_ * S1_ + TPB - 1) / TPB, TPB>>>(eng, nullptr, B_ * S1_, 1);
    {
        dim3 grid(H_ / 128, (B_ * S1_) / 128);
        mma_fused_k<1><<<grid, 256>>>(enc, WtA, eng, P1, v_attn);
    }
    softmax_k<<<B_, 256>>>(smask);
    context_k<<<B_, H_>>>(enc);

    // --- leaf score ---
    concat2_k<<<(BH + TPB - 1) / TPB, TPB>>>(node, ctx, leaf);
    fill_k<<<(BH + TPB - 1) / TPB, TPB>>>(Q1, b_score, BH, H_);
    gemm_split(leaf, W_score, Q1, B_, H_, 2 * H_, 12);
    fill_k<<<(OPC_ * H_ + TPB - 1) / TPB, TPB>>>(Q2c, nullptr, OPC_ * H_, 1);
    gemm_split(opc, W_score + (size_t)2 * H_ * H_, Q2c, OPC_, H_, H_, 6);
    fill_k<<<(B_ * OT_ + TPB - 1) / TPB, TPB>>>(out_score, nullptr, B_ * OT_, 1);
    {
        dim3 grid(H_ / 128, (B_ * S2_) / 128);
        mma_fused_k<2><<<grid, 256>>>(var, WtS, out_score, Q1, v_score);
    }
    finalize_score_k<<<(B_ * OT_ * 32 + TPB - 1) / TPB, TPB>>>(v_score, cmask, out_score);

    // --- remaining outputs ---
    copy_k<<<(BH + TPB - 1) / TPB, TPB>>>(node, out_node, BH);
    copy_k<<<(BH + TPB - 1) / TPB, TPB>>>(ctx,  out_ctx,  BH);
    {
        size_t total4 = (size_t)B_ * OT_ * H_ / 4;
        emb_all_k<<<(unsigned)((total4 + TPB - 1) / TPB), TPB>>>(opc, var, out_emb);
    }
}

// round 5
// speedup vs baseline: 3.4477x; 1.3940x over previous
#include <cuda_runtime.h>
#include <math.h>
#include <stdint.h>

#define B_   256
#define S1_  512
#define S2_  64
#define H_   768
#define OPC_ 64
#define OT_  128
#define NEGV (-1e12f)

// ---------------- scratch (device globals) ----------------------------------
__device__ float g_lc  [B_ * 2 * H_];
__device__ float g_gA  [B_ * H_];
__device__ float g_gB  [B_ * H_];
__device__ float g_gC  [B_ * H_];
__device__ float g_gD  [B_ * H_];
__device__ float g_node[B_ * H_];
__device__ float g_P1  [B_ * H_];
__device__ float g_eng [B_ * S1_];
__device__ float g_ctx [B_ * H_];
__device__ float g_leaf[B_ * 2 * H_];
__device__ float g_Q1  [B_ * H_];
__device__ float g_Q2c [OPC_ * H_];
// transposed weights: Wt[n][k] = W[k][n]
__device__ float g_WtL  [H_ * H_];
__device__ float g_WtLG [H_ * H_];
__device__ float g_WtR  [H_ * 2 * H_];
__device__ float g_WtRG [H_ * 2 * H_];
__device__ float g_WtA1 [H_ * H_];
__device__ float g_WtA2 [H_ * H_];
__device__ float g_WtS12[H_ * 2 * H_];
__device__ float g_WtS3 [H_ * H_];

// ---------------- helpers ------------------------------------------------------
__device__ __forceinline__ float tanh_fast(float x) {
    float y; asm("tanh.approx.f32 %0, %1;" : "=f"(y) : "f"(x)); return y;
}
__device__ __forceinline__ float ftanh(float x) {
    float ax = fabsf(x);
    float e  = __expf(2.0f * ax);
    float r  = 1.0f - __fdividef(2.0f, e + 1.0f);
    return copysignf(r, x);
}
__device__ __forceinline__ float fsig(float x) {
    return __fdividef(1.0f, 1.0f + __expf(-x));
}
__device__ __forceinline__ uint32_t to_tf32(float x) {
    uint32_t r; asm("cvt.rna.tf32.f32 %0, %1;" : "=r"(r) : "f"(x)); return r;
}
__device__ __forceinline__ void mma_tf32(float c[4], const uint32_t a[4],
                                         const uint32_t b[2]) {
    asm volatile(
        "mma.sync.aligned.m16n8k8.row.col.f32.tf32.tf32.f32 "
        "{%0,%1,%2,%3}, {%4,%5,%6,%7}, {%8,%9}, {%0,%1,%2,%3};"
        : "+f"(c[0]), "+f"(c[1]), "+f"(c[2]), "+f"(c[3])
        : "r"(a[0]), "r"(a[1]), "r"(a[2]), "r"(a[3]), "r"(b[0]), "r"(b[1]));
}

// ---------------- unified pipelined tf32 MMA kernel ---------------------------
// C-tile 128m x 128n, BK=16, 256 threads = 8 warps (4 m-bands x 2 n-halves),
// warp tile 32x64. Double-buffered SMEM + register prefetch (1 sync / k-iter).
// A row-major [M,K]; Wt row-major [N][K] (Wt[n][k] = W[k][n]).
// MODE 0: split-K over blockIdx.z; atomicAdd into C (N stride 768), bias preloaded.
// MODE 1: energy out[r] += sum_n v[n]*tanh(aux1[bm>>9, n] + acc)
// MODE 2: score  out[(r>>6)*128 + 64 + (r&63)] += sum_n v[n]*tanh(aux1[r>>6, n] + acc)
template <int MODE>
__global__ __launch_bounds__(256, 2) void mma_k(
    const float* __restrict__ A, const float* __restrict__ Wt,
    float* __restrict__ outv,
    const float* __restrict__ aux1, const float* __restrict__ aux2,
    int M, int K, int niter)
{
    __shared__ uint32_t As[2][16][136];
    __shared__ uint32_t Bs[2][16][136];

    const int tid  = threadIdx.x;
    const int lane = tid & 31;
    const int wid  = tid >> 5;
    const int wm   = wid & 3;
    const int wn   = wid >> 2;
    const int bm   = blockIdx.y * 128;
    const int bn   = blockIdx.x * 128;
    const int kst  = blockIdx.z * niter * 16;

    float acc[2][8][4];
#pragma unroll
    for (int i = 0; i < 2; i++)
#pragma unroll
        for (int j = 0; j < 8; j++)
#pragma unroll
            for (int q = 0; q < 4; q++) acc[i][j][q] = 0.f;

    // loaders: both A and B: row = tid>>1 (0..127), k cols (tid&1)*8 .. +7
    const int l_row = tid >> 1;
    const int l_col = (tid & 1) * 8;
    const bool a_ok = (bm + l_row) < M;
    const float* Ap = A  + (size_t)(bm + l_row) * K + kst + l_col;
    const float* Bp = Wt + (size_t)(bn + l_row) * K + kst + l_col;

    float4 a0, a1, b0, b1;
    if (a_ok) { a0 = *(const float4*)Ap; a1 = *(const float4*)(Ap + 4); }
    else { a0 = make_float4(0.f, 0.f, 0.f, 0.f); a1 = a0; }
    b0 = *(const float4*)Bp;
    b1 = *(const float4*)(Bp + 4);

    auto store_tile = [&](int buf) {
        As[buf][l_col + 0][l_row] = to_tf32(a0.x);
        As[buf][l_col + 1][l_row] = to_tf32(a0.y);
        As[buf][l_col + 2][l_row] = to_tf32(a0.z);
        As[buf][l_col + 3][l_row] = to_tf32(a0.w);
        As[buf][l_col + 4][l_row] = to_tf32(a1.x);
        As[buf][l_col + 5][l_row] = to_tf32(a1.y);
        As[buf][l_col + 6][l_row] = to_tf32(a1.z);
        As[buf][l_col + 7][l_row] = to_tf32(a1.w);
        Bs[buf][l_col + 0][l_row] = to_tf32(b0.x);
        Bs[buf][l_col + 1][l_row] = to_tf32(b0.y);
        Bs[buf][l_col + 2][l_row] = to_tf32(b0.z);
        Bs[buf][l_col + 3][l_row] = to_tf32(b0.w);
        Bs[buf][l_col + 4][l_row] = to_tf32(b1.x);
        Bs[buf][l_col + 5][l_row] = to_tf32(b1.y);
        Bs[buf][l_col + 6][l_row] = to_tf32(b1.z);
        Bs[buf][l_col + 7][l_row] = to_tf32(b1.w);
    };

    store_tile(0);
    __syncthreads();

    const int lk = lane & 3;
    const int lg = lane >> 2;

    for (int c = 0; c < niter; c++) {
        const int cur = c & 1;
        const bool have_next = (c + 1 < niter);
        if (have_next) {
            const float* Ap2 = Ap + (c + 1) * 16;
            const float* Bp2 = Bp + (c + 1) * 16;
            if (a_ok) { a0 = *(const float4*)Ap2; a1 = *(const float4*)(Ap2 + 4); }
            else { a0 = make_float4(0.f, 0.f, 0.f, 0.f); a1 = a0; }
            b0 = *(const float4*)Bp2;
            b1 = *(const float4*)(Bp2 + 4);
        }

#pragma unroll
        for (int kk = 0; kk < 16; kk += 8) {
            uint32_t af[2][4], bf[8][2];
#pragma unroll
            for (int ti = 0; ti < 2; ti++) {
                int m = wm * 32 + ti * 16 + lg;
                af[ti][0] = As[cur][kk + lk][m];
                af[ti][1] = As[cur][kk + lk][m + 8];
                af[ti][2] = As[cur][kk + 4 + lk][m];
                af[ti][3] = As[cur][kk + 4 + lk][m + 8];
            }
#pragma unroll
            for (int nj = 0; nj < 8; nj++) {
                int n = wn * 64 + nj * 8 + lg;
                bf[nj][0] = Bs[cur][kk + lk][n];
                bf[nj][1] = Bs[cur][kk + 4 + lk][n];
            }
#pragma unroll
            for (int ti = 0; ti < 2; ti++)
#pragma unroll
                for (int nj = 0; nj < 8; nj++)
                    mma_tf32(acc[ti][nj], af[ti], bf[nj]);
        }

        if (have_next) store_tile((c + 1) & 1);
        __syncthreads();
    }

    // ---------------- epilogues ----------------
    if (MODE == 0) {
#pragma unroll
        for (int ti = 0; ti < 2; ti++)
#pragma unroll
            for (int nj = 0; nj < 8; nj++) {
                int r0 = bm + wm * 32 + ti * 16 + lg;
                int c0 = bn + wn * 64 + nj * 8 + 2 * lk;
                if (r0 < M) {
                    atomicAdd(&outv[(size_t)r0 * 768 + c0],     acc[ti][nj][0]);
                    atomicAdd(&outv[(size_t)r0 * 768 + c0 + 1], acc[ti][nj][1]);
                }
                if (r0 + 8 < M) {
                    atomicAdd(&outv[(size_t)(r0 + 8) * 768 + c0],     acc[ti][nj][2]);
                    atomicAdd(&outv[(size_t)(r0 + 8) * 768 + c0 + 1], acc[ti][nj][3]);
                }
            }
        return;
    }

    float vv[16];
#pragma unroll
    for (int nj = 0; nj < 8; nj++)
#pragma unroll
        for (int u = 0; u < 2; u++)
            vv[nj * 2 + u] = __ldg(&aux2[bn + wn * 64 + nj * 8 + 2 * lk + u]);

    if (MODE == 1) {
        const int b = bm >> 9;
        float p1v[16];
#pragma unroll
        for (int nj = 0; nj < 8; nj++)
#pragma unroll
            for (int u = 0; u < 2; u++)
                p1v[nj * 2 + u] = __ldg(&aux1[(size_t)b * H_ + bn + wn * 64 + nj * 8 + 2 * lk + u]);
#pragma unroll
        for (int ti = 0; ti < 2; ti++)
#pragma unroll
            for (int half = 0; half < 2; half++) {
                int r = bm + wm * 32 + ti * 16 + lg + half * 8;
                float part = 0.f;
#pragma unroll
                for (int nj = 0; nj < 8; nj++) {
                    part += vv[nj * 2]     * tanh_fast(acc[ti][nj][half * 2]     + p1v[nj * 2]);
                    part += vv[nj * 2 + 1] * tanh_fast(acc[ti][nj][half * 2 + 1] + p1v[nj * 2 + 1]);
                }
                part += __shfl_xor_sync(0xFFFFFFFFu, part, 1);
                part += __shfl_xor_sync(0xFFFFFFFFu, part, 2);
                if (lk == 0) atomicAdd(&outv[r], part);
            }
    } else {
#pragma unroll
        for (int ti = 0; ti < 2; ti++)
#pragma unroll
            for (int half = 0; half < 2; half++) {
                int r = bm + wm * 32 + ti * 16 + lg + half * 8;
                int b = r >> 6;
                const float* q1 = aux1 + (size_t)b * H_;
                float part = 0.f;
#pragma unroll
                for (int nj = 0; nj < 8; nj++) {
                    int n = bn + wn * 64 + nj * 8 + 2 * lk;
                    part += vv[nj * 2]     * tanh_fast(acc[ti][nj][half * 2]     + __ldg(&q1[n]));
                    part += vv[nj * 2 + 1] * tanh_fast(acc[ti][nj][half * 2 + 1] + __ldg(&q1[n + 1]));
                }
                part += __shfl_xor_sync(0xFFFFFFFFu, part, 1);
                part += __shfl_xor_sync(0xFFFFFFFFu, part, 2);
                if (lk == 0) atomicAdd(&outv[(size_t)b * OT_ + OPC_ + (r & 63)], part);
            }
    }
}

// ---------------- small helpers ----------------------------------------------
__global__ void fill_k(float* __restrict__ C, const float* __restrict__ bias,
                       int total, int N)
{
    int i = blockIdx.x * blockDim.x + threadIdx.x;
    if (i < total) C[i] = bias ? bias[i % N] : 0.f;
}

// dst[c][r] = src[r][c]; src is [R][C]; grid (C/32, R/32), block (32,8)
__global__ void transpose_k(const float* __restrict__ src, float* __restrict__ dst,
                            int R, int C)
{
    __shared__ float t[32][33];
    int bx = blockIdx.x * 32, by = blockIdx.y * 32;
    int x = threadIdx.x, y = threadIdx.y;
#pragma unroll
    for (int i = 0; i < 32; i += 8)
        t[y + i][x] = src[(size_t)(by + y + i) * C + bx + x];
    __syncthreads();
#pragma unroll
    for (int i = 0; i < 32; i += 8)
        dst[(size_t)(bx + y + i) * R + by + x] = t[x][y + i];
}

__global__ void concat2_k(const float* __restrict__ x, const float* __restrict__ y,
                          float* __restrict__ out)
{
    int i = blockIdx.x * blockDim.x + threadIdx.x;
    if (i >= B_ * H_) return;
    int b = i / H_, h = i % H_;
    out[(size_t)b * 2 * H_ + h]      = x[i];
    out[(size_t)b * 2 * H_ + H_ + h] = y[i];
}

__global__ void combine_node_k(const int* __restrict__ has_left)
{
    int i = blockIdx.x * blockDim.x + threadIdx.x;
    if (i >= B_ * H_) return;
    int b = i / H_;
    float v = has_left[b] ? ftanh(g_gC[i]) * fsig(g_gD[i])
                          : ftanh(g_gA[i]) * fsig(g_gB[i]);
    g_node[i] = v;
}

__global__ void softmax_k(const int* __restrict__ smask)
{
    __shared__ float red[256];
    int b = blockIdx.x, t = threadIdx.x;
    float* e = g_eng + (size_t)b * S1_;
    const int* m = smask + (size_t)b * S1_;
    float x0 = m[t]       ? NEGV : e[t];
    float x1 = m[t + 256] ? NEGV : e[t + 256];
    red[t] = fmaxf(x0, x1);
    __syncthreads();
    for (int s = 128; s > 0; s >>= 1) {
        if (t < s) red[t] = fmaxf(red[t], red[t + s]);
        __syncthreads();
    }
    float mx = red[0];
    __syncthreads();
    float e0 = __expf(x0 - mx), e1 = __expf(x1 - mx);
    red[t] = e0 + e1;
    __syncthreads();
    for (int s = 128; s > 0; s >>= 1) {
        if (t < s) red[t] += red[t + s];
        __syncthreads();
    }
    float inv = __fdividef(1.f, red[0]);
    e[t] = e0 * inv;
    e[t + 256] = e1 * inv;
}

__global__ void context_k(const float* __restrict__ enc)
{
    int b = blockIdx.x, h = threadIdx.x;
    const float* a = g_eng + (size_t)b * S1_;
    const float* e = enc + (size_t)b * S1_ * H_ + h;
    float acc = 0.f;
#pragma unroll 8
    for (int s = 0; s < S1_; s++)
        acc = fmaf(__ldg(a + s), __ldg(e + (size_t)s * H_), acc);
    g_ctx[(size_t)b * H_ + h] = acc;
}

__global__ void finalize_score_k(const float* __restrict__ vsc,
                                 const int* __restrict__ cmask,
                                 float* __restrict__ score)
{
    int idx = (blockIdx.x * blockDim.x + threadIdx.x) >> 5;
    if (idx >= B_ * OT_) return;
    int lane = threadIdx.x & 31;
    int b = idx >> 7, o = idx & 127;
    if (cmask[idx]) {
        if (lane == 0) score[idx] = NEGV;
        return;
    }
    if (o >= OPC_) return;
    const float* q1 = g_Q1 + (size_t)b * H_;
    const float* q2 = g_Q2c + (size_t)o * H_;
    float acc = 0.f;
    for (int h = lane; h < H_; h += 32)
        acc += vsc[h] * ftanh(q1[h] + q2[h]);
#pragma unroll
    for (int off = 16; off; off >>= 1) acc += __shfl_xor_sync(0xFFFFFFFFu, acc, off);
    if (lane == 0) score[idx] = acc;
}

__global__ void copy_k(const float* __restrict__ src, float* __restrict__ dst, int n)
{
    int i = blockIdx.x * blockDim.x + threadIdx.x;
    if (i < n) dst[i] = src[i];
}

__global__ void emb_all_k(const float* __restrict__ opc, const float* __restrict__ var,
                          float* __restrict__ dst)
{
    size_t i = (size_t)blockIdx.x * blockDim.x + threadIdx.x;
    const size_t total = (size_t)B_ * OT_ * H_ / 4;
    if (i >= total) return;
    size_t elem = i * 4;
    int h = (int)(elem % H_);
    size_t bo = elem / H_;
    int o = (int)(bo % OT_);
    int b = (int)(bo / OT_);
    float4 v;
    if (o < OPC_) v = *(const float4*)(opc + (size_t)o * H_ + h);
    else          v = *(const float4*)(var + ((size_t)b * S2_ + (o - OPC_)) * H_ + h);
    ((float4*)dst)[i] = v;
}

// ---------------- launch -------------------------------------------------------
extern "C" void kernel_launch(void* const* d_in, const int* in_sizes, int n_in,
                              void* d_out, int out_size)
{
    (void)in_sizes; (void)n_in; (void)out_size;
    const float* current = (const float*)d_in[0];
    const float* left    = (const float*)d_in[1];
    const float* enc     = (const float*)d_in[2];
    const float* var     = (const float*)d_in[3];
    const float* opc     = (const float*)d_in[4];
    const float* W_l     = (const float*)d_in[5];
    const float* b_l     = (const float*)d_in[6];
    const float* W_lg    = (const float*)d_in[7];
    const float* b_lg    = (const float*)d_in[8];
    const float* W_r     = (const float*)d_in[9];
    const float* b_r     = (const float*)d_in[10];
    const float* W_rg    = (const float*)d_in[11];
    const float* b_rg    = (const float*)d_in[12];
    const float* W_attn  = (const float*)d_in[13];
    const float* b_attn  = (const float*)d_in[14];
    const float* v_attn  = (const float*)d_in[15];
    const float* W_score = (const float*)d_in[16];
    const float* b_score = (const float*)d_in[17];
    const float* v_score = (const float*)d_in[18];
    const int*   has_left = (const int*)d_in[19];
    const int*   smask    = (const int*)d_in[20];
    const int*   cmask    = (const int*)d_in[21];

    float *lc, *gA, *gB, *gC, *gD, *node, *P1, *eng, *ctx, *leaf, *Q1, *Q2c;
    float *WtL, *WtLG, *WtR, *WtRG, *WtA1, *WtA2, *WtS12, *WtS3;
    cudaGetSymbolAddress((void**)&lc,   g_lc);
    cudaGetSymbolAddress((void**)&gA,   g_gA);
    cudaGetSymbolAddress((void**)&gB,   g_gB);
    cudaGetSymbolAddress((void**)&gC,   g_gC);
    cudaGetSymbolAddress((void**)&gD,   g_gD);
    cudaGetSymbolAddress((void**)&node, g_node);
    cudaGetSymbolAddress((void**)&P1,   g_P1);
    cudaGetSymbolAddress((void**)&eng,  g_eng);
    cudaGetSymbolAddress((void**)&ctx,  g_ctx);
    cudaGetSymbolAddress((void**)&leaf, g_leaf);
    cudaGetSymbolAddress((void**)&Q1,   g_Q1);
    cudaGetSymbolAddress((void**)&Q2c,  g_Q2c);
    cudaGetSymbolAddress((void**)&WtL,  g_WtL);
    cudaGetSymbolAddress((void**)&WtLG, g_WtLG);
    cudaGetSymbolAddress((void**)&WtR,  g_WtR);
    cudaGetSymbolAddress((void**)&WtRG, g_WtRG);
    cudaGetSymbolAddress((void**)&WtA1, g_WtA1);
    cudaGetSymbolAddress((void**)&WtA2, g_WtA2);
    cudaGetSymbolAddress((void**)&WtS12, g_WtS12);
    cudaGetSymbolAddress((void**)&WtS3, g_WtS3);

    float* out       = (float*)d_out;
    float* out_score = out;
    float* out_node  = out_score + B_ * OT_;
    float* out_ctx   = out_node + B_ * H_;
    float* out_emb   = out_ctx + B_ * H_;

    const int BH = B_ * H_;
    const int TPB = 256;
    dim3 tb(32, 8);

    // --- transposes (independent) ---
    transpose_k<<<dim3(24, 24), tb>>>(W_l,  WtL,  H_, H_);
    transpose_k<<<dim3(24, 24), tb>>>(W_lg, WtLG, H_, H_);
    transpose_k<<<dim3(24, 48), tb>>>(W_r,  WtR,  2 * H_, H_);
    transpose_k<<<dim3(24, 48), tb>>>(W_rg, WtRG, 2 * H_, H_);
    transpose_k<<<dim3(24, 24), tb>>>(W_attn,                     WtA1, H_, H_);
    transpose_k<<<dim3(24, 24), tb>>>(W_attn + (size_t)H_ * H_,   WtA2, H_, H_);
    transpose_k<<<dim3(24, 48), tb>>>(W_score,                    WtS12, 2 * H_, H_);
    transpose_k<<<dim3(24, 24), tb>>>(W_score + (size_t)2 * H_ * H_, WtS3, H_, H_);

    // --- node: four gate GEMMs (tf32 MMA, split-K, bias preloaded) ---
    concat2_k<<<(BH + TPB - 1) / TPB, TPB>>>(left, current, lc);
    fill_k<<<(BH + TPB - 1) / TPB, TPB>>>(gA, b_l,  BH, H_);
    fill_k<<<(BH + TPB - 1) / TPB, TPB>>>(gB, b_lg, BH, H_);
    fill_k<<<(BH + TPB - 1) / TPB, TPB>>>(gC, b_r,  BH, H_);
    fill_k<<<(BH + TPB - 1) / TPB, TPB>>>(gD, b_rg, BH, H_);
    mma_k<0><<<dim3(6, 2, 6),  256>>>(current, WtL,  gA, nullptr, nullptr, B_, H_, 8);
    mma_k<0><<<dim3(6, 2, 6),  256>>>(current, WtLG, gB, nullptr, nullptr, B_, H_, 8);
    mma_k<0><<<dim3(6, 2, 12), 256>>>(lc, WtR,  gC, nullptr, nullptr, B_, 2 * H_, 8);
    mma_k<0><<<dim3(6, 2, 12), 256>>>(lc, WtRG, gD, nullptr, nullptr, B_, 2 * H_, 8);
    combine_node_k<<<(BH + TPB - 1) / TPB, TPB>>>(has_left);

    // --- attention ---
    fill_k<<<(BH + TPB - 1) / TPB, TPB>>>(P1, b_attn, BH, H_);
    mma_k<0><<<dim3(6, 2, 6), 256>>>(node, WtA1, P1, nullptr, nullptr, B_, H_, 8);
    fill_k<<<(B_ * S1_ + TPB - 1) / TPB, TPB>>>(eng, nullptr, B_ * S1_, 1);
    mma_k<1><<<dim3(6, (B_ * S1_) / 128, 1), 256>>>(enc, WtA2, eng, P1, v_attn,
                                                    B_ * S1_, H_, H_ / 16);
    softmax_k<<<B_, 256>>>(smask);
    context_k<<<B_, H_>>>(enc);

    // --- leaf score ---
    concat2_k<<<(BH + TPB - 1) / TPB, TPB>>>(node, ctx, leaf);
    fill_k<<<(BH + TPB - 1) / TPB, TPB>>>(Q1, b_score, BH, H_);
    mma_k<0><<<dim3(6, 2, 12), 256>>>(leaf, WtS12, Q1, nullptr, nullptr, B_, 2 * H_, 8);
    fill_k<<<(OPC_ * H_ + TPB - 1) / TPB, TPB>>>(Q2c, nullptr, OPC_ * H_, 1);
    mma_k<0><<<dim3(6, 1, 6), 256>>>(opc, WtS3, Q2c, nullptr, nullptr, OPC_, H_, 8);
    fill_k<<<(B_ * OT_ + TPB - 1) / TPB, TPB>>>(out_score, nullptr, B_ * OT_, 1);
    mma_k<2><<<dim3(6, (B_ * S2_) / 128, 1), 256>>>(var, WtS3, out_score, Q1, v_score,
                                                    B_ * S2_, H_, H_ / 16);
    finalize_score_k<<<(B_ * OT_ * 32 + TPB - 1) / TPB, TPB>>>(v_score, cmask, out_score);

    // --- remaining outputs ---
    copy_k<<<(BH + TPB - 1) / TPB, TPB>>>(node, out_node, BH);
    copy_k<<<(BH + TPB - 1) / TPB, TPB>>>(ctx,  out_ctx,  BH);
    {
        size_t total4 = (size_t)B_ * OT_ * H_ / 4;
        emb_all_k<<<(unsigned)((total4 + TPB - 1) / TPB), TPB>>>(opc, var, out_emb);
    }
}

// round 6
// speedup vs baseline: 4.3285x; 1.2555x over previous
#include <cuda_runtime.h>
#include <math.h>
#include <stdint.h>

#define B_   256
#define S1_  512
#define S2_  64
#define H_   768
#define OPC_ 64
#define OT_  128
#define NEGV (-1e12f)

// ---------------- scratch (device globals) ----------------------------------
__device__ float g_gA  [B_ * H_];
__device__ float g_gB  [B_ * H_];
__device__ float g_gC  [B_ * H_];
__device__ float g_gD  [B_ * H_];
__device__ float g_node[B_ * H_];
__device__ float g_P1  [B_ * H_];
__device__ float g_eng [B_ * S1_];
__device__ float g_ctx [B_ * H_];
__device__ float g_Q1  [B_ * H_];
__device__ float g_Q2c [OPC_ * H_];
// tf32-rounded activations (MMA A-operands)
__device__ float g_encR [(size_t)B_ * S1_ * H_];
__device__ float g_varR [(size_t)B_ * S2_ * H_];
__device__ float g_curR [B_ * H_];
__device__ float g_opcR [OPC_ * H_];
__device__ float g_lcR  [B_ * 2 * H_];
__device__ float g_nodeR[B_ * H_];
__device__ float g_leafR[B_ * 2 * H_];
// tf32-rounded transposed weights: Wt[n][k] = W[k][n]
__device__ float g_WtL  [H_ * H_];
__device__ float g_WtLG [H_ * H_];
__device__ float g_WtA1 [H_ * H_];
__device__ float g_WtA2 [H_ * H_];
__device__ float g_WtS3 [H_ * H_];
__device__ float g_WtR  [H_ * 2 * H_];
__device__ float g_WtRG [H_ * 2 * H_];
__device__ float g_WtS12[H_ * 2 * H_];

// ---------------- helpers ------------------------------------------------------
__device__ __forceinline__ float tanh_fast(float x) {
    float y; asm("tanh.approx.f32 %0, %1;" : "=f"(y) : "f"(x)); return y;
}
__device__ __forceinline__ float ftanh(float x) {
    float ax = fabsf(x);
    float e  = __expf(2.0f * ax);
    float r  = 1.0f - __fdividef(2.0f, e + 1.0f);
    return copysignf(r, x);
}
__device__ __forceinline__ float fsig(float x) {
    return __fdividef(1.0f, 1.0f + __expf(-x));
}
__device__ __forceinline__ float rtf(float x) {   // rna round to tf32, as float bits
    uint32_t r; asm("cvt.rna.tf32.f32 %0, %1;" : "=r"(r) : "f"(x));
    return __uint_as_float(r);
}
__device__ __forceinline__ uint32_t smem_u32(const void* p) {
    uint32_t a;
    asm("{ .reg .u64 t; cvta.to.shared.u64 t, %1; cvt.u32.u64 %0, t; }" : "=r"(a) : "l"(p));
    return a;
}
__device__ __forceinline__ void cp16(uint32_t saddr, const float* g, uint32_t sz) {
    asm volatile("cp.async.cg.shared.global [%0], [%1], 16, %2;"
                 :: "r"(saddr), "l"(g), "r"(sz) : "memory");
}
__device__ __forceinline__ void cp_commit() {
    asm volatile("cp.async.commit_group;" ::: "memory");
}
__device__ __forceinline__ void cp_wait2() {
    asm volatile("cp.async.wait_group 2;" ::: "memory");
}
__device__ __forceinline__ void mma_tf32(float c[4], const uint32_t a[4],
                                         const uint32_t b[2]) {
    asm volatile(
        "mma.sync.aligned.m16n8k8.row.col.f32.tf32.tf32.f32 "
        "{%0,%1,%2,%3}, {%4,%5,%6,%7}, {%8,%9}, {%0,%1,%2,%3};"
        : "+f"(c[0]), "+f"(c[1]), "+f"(c[2]), "+f"(c[3])
        : "r"(a[0]), "r"(a[1]), "r"(a[2]), "r"(a[3]), "r"(b[0]), "r"(b[1]));
}

// ---------------- pipelined tf32 MMA kernel (cp.async 4-stage) -----------------
// C-tile 128m x 128n, BK=16, 256 thr = 8 warps (4 m-bands x 2 n-halves), warp 32x64.
// A row-major [M,K] (pre-rounded tf32); Wt row-major [N][K] (pre-rounded).
// SMEM: per stage As[128][20], Bs[128][20] (pad 20 => conflict-free LDS & STS).
// MODE 0: split-K (blockIdx.z), atomicAdd into C[M,768] (bias preloaded).
// MODE 1: energy out[r] += sum_n v[n]*tanh(aux1[bm>>9, n] + acc)
// MODE 2: score  out[(r>>6)*128+64+(r&63)] += sum_n v[n]*tanh(aux1[r>>6, n] + acc)
#define AS_ (128 * 20)
template <int MODE>
__global__ __launch_bounds__(256, 2) void mma_k(
    const float* __restrict__ A, const float* __restrict__ Wt,
    float* __restrict__ outv,
    const float* __restrict__ aux1, const float* __restrict__ aux2,
    int M, int K, int niter)
{
    extern __shared__ __align__(16) float sm[];
    float* Asm = sm;                 // [4][128][20]
    float* Bsm = sm + 4 * AS_;       // [4][128][20]
    const uint32_t sA = smem_u32(Asm);
    const uint32_t sB = smem_u32(Bsm);

    const int tid  = threadIdx.x;
    const int lane = tid & 31;
    const int wid  = tid >> 5;
    const int wm   = wid & 3;
    const int wn   = wid >> 2;
    const int bm   = blockIdx.y * 128;
    const int bn   = blockIdx.x * 128;
    const int kst  = blockIdx.z * niter * 16;

    float acc[2][8][4];
#pragma unroll
    for (int i = 0; i < 2; i++)
#pragma unroll
        for (int j = 0; j < 8; j++)
#pragma unroll
            for (int q = 0; q < 4; q++) acc[i][j][q] = 0.f;

    const int l_row = tid >> 1;
    const int c0    = (tid & 1) * 8;
    const uint32_t a_sz = ((bm + l_row) < M) ? 16u : 0u;
    const float* Ap = A  + (size_t)(bm + l_row) * K + kst + c0;
    const float* Bp = Wt + (size_t)(bn + l_row) * K + kst + c0;
    const uint32_t dstA = sA + (uint32_t)(l_row * 20 + c0) * 4u;
    const uint32_t dstB = sB + (uint32_t)(l_row * 20 + c0) * 4u;

    auto issue = [&](int stage, int kt) {
        const float* a = Ap + kt * 16;
        const float* b = Bp + kt * 16;
        uint32_t so = (uint32_t)(stage * AS_) * 4u;
        cp16(dstA + so,      a,     a_sz);
        cp16(dstA + so + 16, a + 4, a_sz);
        cp16(dstB + so,      b,     16u);
        cp16(dstB + so + 16, b + 4, 16u);
    };

    // prologue: 3 stages in flight
#pragma unroll
    for (int s = 0; s < 3; s++) {
        if (s < niter) issue(s, s);
        cp_commit();
    }

    const int lk = lane & 3;
    const int lg = lane >> 2;

    for (int c = 0; c < niter; c++) {
        cp_wait2();
        __syncthreads();
        const float* Asc = Asm + (c & 3) * AS_;
        const float* Bsc = Bsm + (c & 3) * AS_;

#pragma unroll
        for (int kk = 0; kk < 16; kk += 8) {
            uint32_t af[2][4], bf[8][2];
#pragma unroll
            for (int ti = 0; ti < 2; ti++) {
                int m = wm * 32 + ti * 16 + lg;
                af[ti][0] = __float_as_uint(Asc[m * 20 + kk + lk]);
                af[ti][1] = __float_as_uint(Asc[(m + 8) * 20 + kk + lk]);
                af[ti][2] = __float_as_uint(Asc[m * 20 + kk + 4 + lk]);
                af[ti][3] = __float_as_uint(Asc[(m + 8) * 20 + kk + 4 + lk]);
            }
#pragma unroll
            for (int nj = 0; nj < 8; nj++) {
                int n = wn * 64 + nj * 8 + lg;
                bf[nj][0] = __float_as_uint(Bsc[n * 20 + kk + lk]);
                bf[nj][1] = __float_as_uint(Bsc[n * 20 + kk + 4 + lk]);
            }
#pragma unroll
            for (int ti = 0; ti < 2; ti++)
#pragma unroll
                for (int nj = 0; nj < 8; nj++)
                    mma_tf32(acc[ti][nj], af[ti], bf[nj]);
        }

        if (c + 3 < niter) issue((c + 3) & 3, c + 3);
        cp_commit();
    }

    // ---------------- epilogues ----------------
    if (MODE == 0) {
#pragma unroll
        for (int ti = 0; ti < 2; ti++)
#pragma unroll
            for (int nj = 0; nj < 8; nj++) {
                int r0 = bm + wm * 32 + ti * 16 + lg;
                int cc = bn + wn * 64 + nj * 8 + 2 * lk;
                if (r0 < M) {
                    atomicAdd(&outv[(size_t)r0 * 768 + cc],     acc[ti][nj][0]);
                    atomicAdd(&outv[(size_t)r0 * 768 + cc + 1], acc[ti][nj][1]);
                }
                if (r0 + 8 < M) {
                    atomicAdd(&outv[(size_t)(r0 + 8) * 768 + cc],     acc[ti][nj][2]);
                    atomicAdd(&outv[(size_t)(r0 + 8) * 768 + cc + 1], acc[ti][nj][3]);
                }
            }
        return;
    }

    float vv[16];
#pragma unroll
    for (int nj = 0; nj < 8; nj++)
#pragma unroll
        for (int u = 0; u < 2; u++)
            vv[nj * 2 + u] = __ldg(&aux2[bn + wn * 64 + nj * 8 + 2 * lk + u]);

    if (MODE == 1) {
        const int b = bm >> 9;
        float p1v[16];
#pragma unroll
        for (int nj = 0; nj < 8; nj++)
#pragma unroll
            for (int u = 0; u < 2; u++)
                p1v[nj * 2 + u] = __ldg(&aux1[(size_t)b * H_ + bn + wn * 64 + nj * 8 + 2 * lk + u]);
#pragma unroll
        for (int ti = 0; ti < 2; ti++)
#pragma unroll
            for (int half = 0; half < 2; half++) {
                int r = bm + wm * 32 + ti * 16 + lg + half * 8;
                float part = 0.f;
#pragma unroll
                for (int nj = 0; nj < 8; nj++) {
                    part += vv[nj * 2]     * tanh_fast(acc[ti][nj][half * 2]     + p1v[nj * 2]);
                    part += vv[nj * 2 + 1] * tanh_fast(acc[ti][nj][half * 2 + 1] + p1v[nj * 2 + 1]);
                }
                part += __shfl_xor_sync(0xFFFFFFFFu, part, 1);
                part += __shfl_xor_sync(0xFFFFFFFFu, part, 2);
                if (lk == 0) atomicAdd(&outv[r], part);
            }
    } else {
#pragma unroll
        for (int ti = 0; ti < 2; ti++)
#pragma unroll
            for (int half = 0; half < 2; half++) {
                int r = bm + wm * 32 + ti * 16 + lg + half * 8;
                int b = r >> 6;
                const float* q1 = aux1 + (size_t)b * H_;
                float part = 0.f;
#pragma unroll
                for (int nj = 0; nj < 8; nj++) {
                    int n = bn + wn * 64 + nj * 8 + 2 * lk;
                    part += vv[nj * 2]     * tanh_fast(acc[ti][nj][half * 2]     + __ldg(&q1[n]));
                    part += vv[nj * 2 + 1] * tanh_fast(acc[ti][nj][half * 2 + 1] + __ldg(&q1[n + 1]));
                }
                part += __shfl_xor_sync(0xFFFFFFFFu, part, 1);
                part += __shfl_xor_sync(0xFFFFFFFFu, part, 2);
                if (lk == 0) atomicAdd(&outv[(size_t)b * OT_ + OPC_ + (r & 63)], part);
            }
    }
}

// ---------------- small helpers ----------------------------------------------
// one launch: 6 bias-fills of [B,768] + three zero ranges
__global__ void fill_mega_k(
    float* dA, const float* bA, float* dB, const float* bB,
    float* dC, const float* bC, float* dD, const float* bD,
    float* dE, const float* bE, float* dF, const float* bF,
    float* z1, int n1, float* z2, int n2, float* z3, int n3)
{
    const int BH = B_ * H_;
    int i = blockIdx.x * blockDim.x + threadIdx.x;
    if (i < 6 * BH) {
        int s = i / BH, j = i % BH, h = j % H_;
        switch (s) {
            case 0: dA[j] = bA[h]; break;
            case 1: dB[j] = bB[h]; break;
            case 2: dC[j] = bC[h]; break;
            case 3: dD[j] = bD[h]; break;
            case 4: dE[j] = bE[h]; break;
            default: dF[j] = bF[h]; break;
        }
        return;
    }
    i -= 6 * BH;
    if (i < n1) { z1[i] = 0.f; return; }
    i -= n1;
    if (i < n2) { z2[i] = 0.f; return; }
    i -= n2;
    if (i < n3) z3[i] = 0.f;
}

__global__ void round_k(const float* __restrict__ src, float* __restrict__ dst, int n4)
{
    int i = blockIdx.x * blockDim.x + threadIdx.x;
    if (i >= n4) return;
    float4 v = ((const float4*)src)[i];
    v.x = rtf(v.x); v.y = rtf(v.y); v.z = rtf(v.z); v.w = rtf(v.w);
    ((float4*)dst)[i] = v;
}

// batched 768x768 transposes (tf32-rounded): z selects pair
__global__ void transpose5_k(const float* s0, float* d0, const float* s1, float* d1,
                             const float* s2, float* d2, const float* s3, float* d3,
                             const float* s4, float* d4)
{
    __shared__ float t[32][33];
    const float* src; float* dst;
    switch (blockIdx.z) {
        case 0: src = s0; dst = d0; break;
        case 1: src = s1; dst = d1; break;
        case 2: src = s2; dst = d2; break;
        case 3: src = s3; dst = d3; break;
        default: src = s4; dst = d4; break;
    }
    int bx = blockIdx.x * 32, by = blockIdx.y * 32;
    int x = threadIdx.x, y = threadIdx.y;
#pragma unroll
    for (int i = 0; i < 32; i += 8)
        t[y + i][x] = src[(size_t)(by + y + i) * H_ + bx + x];
    __syncthreads();
#pragma unroll
    for (int i = 0; i < 32; i += 8)
        dst[(size_t)(bx + y + i) * H_ + by + x] = rtf(t[x][y + i]);
}

// batched 1536x768 transposes (tf32-rounded)
__global__ void transpose3_k(const float* s0, float* d0, const float* s1, float* d1,
                             const float* s2, float* d2)
{
    __shared__ float t[32][33];
    const float* src; float* dst;
    switch (blockIdx.z) {
        case 0: src = s0; dst = d0; break;
        case 1: src = s1; dst = d1; break;
        default: src = s2; dst = d2; break;
    }
    int bx = blockIdx.x * 32, by = blockIdx.y * 32;   // grid (24, 48)
    int x = threadIdx.x, y = threadIdx.y;
#pragma unroll
    for (int i = 0; i < 32; i += 8)
        t[y + i][x] = src[(size_t)(by + y + i) * H_ + bx + x];
    __syncthreads();
#pragma unroll
    for (int i = 0; i < 32; i += 8)
        dst[(size_t)(bx + y + i) * (2 * H_) + by + x] = rtf(t[x][y + i]);
}

// out[b,0:H]=x, out[b,H:2H]=y, tf32-rounded (MMA-A operand)
__global__ void concat2R_k(const float* __restrict__ x, const float* __restrict__ y,
                           float* __restrict__ out)
{
    int i = blockIdx.x * blockDim.x + threadIdx.x;
    if (i >= B_ * H_) return;
    int b = i / H_, h = i % H_;
    out[(size_t)b * 2 * H_ + h]      = rtf(x[i]);
    out[(size_t)b * 2 * H_ + H_ + h] = rtf(y[i]);
}

__global__ void combine_node_k(const int* __restrict__ has_left,
                               float* __restrict__ out_node)
{
    int i = blockIdx.x * blockDim.x + threadIdx.x;
    if (i >= B_ * H_) return;
    int b = i / H_;
    float v = has_left[b] ? ftanh(g_gC[i]) * fsig(g_gD[i])
                          : ftanh(g_gA[i]) * fsig(g_gB[i]);
    g_node[i] = v;
    g_nodeR[i] = rtf(v);
    out_node[i] = v;
}

__global__ void softmax_k(const int* __restrict__ smask)
{
    __shared__ float red[256];
    int b = blockIdx.x, t = threadIdx.x;
    float* e = g_eng + (size_t)b * S1_;
    const int* m = smask + (size_t)b * S1_;
    float x0 = m[t]       ? NEGV : e[t];
    float x1 = m[t + 256] ? NEGV : e[t + 256];
    red[t] = fmaxf(x0, x1);
    __syncthreads();
    for (int s = 128; s > 0; s >>= 1) {
        if (t < s) red[t] = fmaxf(red[t], red[t + s]);
        __syncthreads();
    }
    float mx = red[0];
    __syncthreads();
    float e0 = __expf(x0 - mx), e1 = __expf(x1 - mx);
    red[t] = e0 + e1;
    __syncthreads();
    for (int s = 128; s > 0; s >>= 1) {
        if (t < s) red[t] += red[t + s];
        __syncthreads();
    }
    float inv = __fdividef(1.f, red[0]);
    e[t] = e0 * inv;
    e[t + 256] = e1 * inv;
}

__global__ void context_k(const float* __restrict__ enc, float* __restrict__ out_ctx)
{
    int b = blockIdx.x, h = threadIdx.x;
    const float* a = g_eng + (size_t)b * S1_;
    const float* e = enc + (size_t)b * S1_ * H_ + h;
    float acc = 0.f;
#pragma unroll 8
    for (int s = 0; s < S1_; s++)
        acc = fmaf(__ldg(a + s), __ldg(e + (size_t)s * H_), acc);
    g_ctx[(size_t)b * H_ + h] = acc;
    out_ctx[(size_t)b * H_ + h] = acc;
}

__global__ void finalize_score_k(const float* __restrict__ vsc,
                                 const int* __restrict__ cmask,
                                 float* __restrict__ score)
{
    int idx = (blockIdx.x * blockDim.x + threadIdx.x) >> 5;
    if (idx >= B_ * OT_) return;
    int lane = threadIdx.x & 31;
    int b = idx >> 7, o = idx & 127;
    if (cmask[idx]) {
        if (lane == 0) score[idx] = NEGV;
        return;
    }
    if (o >= OPC_) return;
    const float* q1 = g_Q1 + (size_t)b * H_;
    const float* q2 = g_Q2c + (size_t)o * H_;
    float acc = 0.f;
    for (int h = lane; h < H_; h += 32)
        acc += vsc[h] * ftanh(q1[h] + q2[h]);
#pragma unroll
    for (int off = 16; off; off >>= 1) acc += __shfl_xor_sync(0xFFFFFFFFu, acc, off);
    if (lane == 0) score[idx] = acc;
}

__global__ void emb_all_k(const float* __restrict__ opc, const float* __restrict__ var,
                          float* __restrict__ dst)
{
    size_t i = (size_t)blockIdx.x * blockDim.x + threadIdx.x;
    const size_t total = (size_t)B_ * OT_ * H_ / 4;
    if (i >= total) return;
    size_t elem = i * 4;
    int h = (int)(elem % H_);
    size_t bo = elem / H_;
    int o = (int)(bo % OT_);
    int b = (int)(bo / OT_);
    float4 v;
    if (o < OPC_) v = *(const float4*)(opc + (size_t)o * H_ + h);
    else          v = *(const float4*)(var + ((size_t)b * S2_ + (o - OPC_)) * H_ + h);
    ((float4*)dst)[i] = v;
}

// ---------------- launch -------------------------------------------------------
#define SMEM_MMA (8 * AS_ * 4)   // 4 stages x (A+B) x 128x20 floats = 81920 B

extern "C" void kernel_launch(void* const* d_in, const int* in_sizes, int n_in,
                              void* d_out, int out_size)
{
    (void)in_sizes; (void)n_in; (void)out_size;
    const float* current = (const float*)d_in[0];
    const float* left    = (const float*)d_in[1];
    const float* enc     = (const float*)d_in[2];
    const float* var     = (const float*)d_in[3];
    const float* opc     = (const float*)d_in[4];
    const float* W_l     = (const float*)d_in[5];
    const float* b_l     = (const float*)d_in[6];
    const float* W_lg    = (const float*)d_in[7];
    const float* b_lg    = (const float*)d_in[8];
    const float* W_r     = (const float*)d_in[9];
    const float* b_r     = (const float*)d_in[10];
    const float* W_rg    = (const float*)d_in[11];
    const float* b_rg    = (const float*)d_in[12];
    const float* W_attn  = (const float*)d_in[13];
    const float* b_attn  = (const float*)d_in[14];
    const float* v_attn  = (const float*)d_in[15];
    const float* W_score = (const float*)d_in[16];
    const float* b_score = (const float*)d_in[17];
    const float* v_score = (const float*)d_in[18];
    const int*   has_left = (const int*)d_in[19];
    const int*   smask    = (const int*)d_in[20];
    const int*   cmask    = (const int*)d_in[21];

    float *gA, *gB, *gC, *gD, *node, *P1, *eng, *ctx, *Q1, *Q2c;
    float *encR, *varR, *curR, *opcR, *lcR, *nodeR, *leafR;
    float *WtL, *WtLG, *WtA1, *WtA2, *WtS3, *WtR, *WtRG, *WtS12;
    cudaGetSymbolAddress((void**)&gA,   g_gA);
    cudaGetSymbolAddress((void**)&gB,   g_gB);
    cudaGetSymbolAddress((void**)&gC,   g_gC);
    cudaGetSymbolAddress((void**)&gD,   g_gD);
    cudaGetSymbolAddress((void**)&node, g_node);
    cudaGetSymbolAddress((void**)&P1,   g_P1);
    cudaGetSymbolAddress((void**)&eng,  g_eng);
    cudaGetSymbolAddress((void**)&ctx,  g_ctx);
    cudaGetSymbolAddress((void**)&Q1,   g_Q1);
    cudaGetSymbolAddress((void**)&Q2c,  g_Q2c);
    cudaGetSymbolAddress((void**)&encR, g_encR);
    cudaGetSymbolAddress((void**)&varR, g_varR);
    cudaGetSymbolAddress((void**)&curR, g_curR);
    cudaGetSymbolAddress((void**)&opcR, g_opcR);
    cudaGetSymbolAddress((void**)&lcR,  g_lcR);
    cudaGetSymbolAddress((void**)&nodeR, g_nodeR);
    cudaGetSymbolAddress((void**)&leafR, g_leafR);
    cudaGetSymbolAddress((void**)&WtL,  g_WtL);
    cudaGetSymbolAddress((void**)&WtLG, g_WtLG);
    cudaGetSymbolAddress((void**)&WtA1, g_WtA1);
    cudaGetSymbolAddress((void**)&WtA2, g_WtA2);
    cudaGetSymbolAddress((void**)&WtS3, g_WtS3);
    cudaGetSymbolAddress((void**)&WtR,  g_WtR);
    cudaGetSymbolAddress((void**)&WtRG, g_WtRG);
    cudaGetSymbolAddress((void**)&WtS12, g_WtS12);

    float* out       = (float*)d_out;
    float* out_score = out;
    float* out_node  = out_score + B_ * OT_;
    float* out_ctx   = out_node + B_ * H_;
    float* out_emb   = out_ctx + B_ * H_;

    const int BH = B_ * H_;
    const int TPB = 256;

    cudaFuncSetAttribute(mma_k<0>, cudaFuncAttributeMaxDynamicSharedMemorySize, SMEM_MMA);
    cudaFuncSetAttribute(mma_k<1>, cudaFuncAttributeMaxDynamicSharedMemorySize, SMEM_MMA);
    cudaFuncSetAttribute(mma_k<2>, cudaFuncAttributeMaxDynamicSharedMemorySize, SMEM_MMA);

    // --- fills + roundings + transposes (no interdependencies) ---
    {
        int total = 6 * BH + B_ * S1_ + B_ * OT_ + OPC_ * H_;
        fill_mega_k<<<(total + TPB - 1) / TPB, TPB>>>(
            gA, b_l, gB, b_lg, gC, b_r, gD, b_rg, P1, b_attn, Q1, b_score,
            eng, B_ * S1_, out_score, B_ * OT_, Q2c, OPC_ * H_);
    }
    round_k<<<(BH / 4 + TPB - 1) / TPB, TPB>>>(current, curR, BH / 4);
    round_k<<<(OPC_ * H_ / 4 + TPB - 1) / TPB, TPB>>>(opc, opcR, OPC_ * H_ / 4);
    round_k<<<(B_ * S2_ * H_ / 4 + TPB - 1) / TPB, TPB>>>(var, varR, B_ * S2_ * H_ / 4);
    {
        int n4 = B_ * S1_ * (H_ / 4);
        round_k<<<(n4 + TPB - 1) / TPB, TPB>>>(enc, encR, n4);
    }
    transpose5_k<<<dim3(24, 24, 5), dim3(32, 8)>>>(
        W_l, WtL, W_lg, WtLG, W_attn, WtA1, W_attn + (size_t)H_ * H_, WtA2,
        W_score + (size_t)2 * H_ * H_, WtS3);
    transpose3_k<<<dim3(24, 48, 3), dim3(32, 8)>>>(W_r, WtR, W_rg, WtRG, W_score, WtS12);
    concat2R_k<<<(BH + TPB - 1) / TPB, TPB>>>(left, current, lcR);

    // --- node: four gate GEMMs ---
    mma_k<0><<<dim3(6, 2, 6),  256, SMEM_MMA>>>(curR, WtL,  gA, nullptr, nullptr, B_, H_, 8);
    mma_k<0><<<dim3(6, 2, 6),  256, SMEM_MMA>>>(curR, WtLG, gB, nullptr, nullptr, B_, H_, 8);
    mma_k<0><<<dim3(6, 2, 12), 256, SMEM_MMA>>>(lcR, WtR,  gC, nullptr, nullptr, B_, 2 * H_, 8);
    mma_k<0><<<dim3(6, 2, 12), 256, SMEM_MMA>>>(lcR, WtRG, gD, nullptr, nullptr, B_, 2 * H_, 8);
    combine_node_k<<<(BH + TPB - 1) / TPB, TPB>>>(has_left, out_node);

    // --- attention ---
    mma_k<0><<<dim3(6, 2, 6), 256, SMEM_MMA>>>(nodeR, WtA1, P1, nullptr, nullptr, B_, H_, 8);
    mma_k<1><<<dim3(6, (B_ * S1_) / 128, 1), 256, SMEM_MMA>>>(encR, WtA2, eng, P1, v_attn,
                                                              B_ * S1_, H_, 48);
    softmax_k<<<B_, 256>>>(smask);
    context_k<<<B_, H_>>>(encR, out_ctx);

    // --- leaf score ---
    concat2R_k<<<(BH + TPB - 1) / TPB, TPB>>>(node, ctx, leafR);
    mma_k<0><<<dim3(6, 2, 12), 256, SMEM_MMA>>>(leafR, WtS12, Q1, nullptr, nullptr, B_, 2 * H_, 8);
    mma_k<0><<<dim3(6, 1, 6),  256, SMEM_MMA>>>(opcR, WtS3, Q2c, nullptr, nullptr, OPC_, H_, 8);
    mma_k<2><<<dim3(6, (B_ * S2_) / 128, 1), 256, SMEM_MMA>>>(varR, WtS3, out_score, Q1, v_score,
                                                              B_ * S2_, H_, 48);
    finalize_score_k<<<(B_ * OT_ * 32 + TPB - 1) / TPB, TPB>>>(v_score, cmask, out_score);

    // --- emb_all output (exact copies of originals) ---
    {
        size_t total4 = (size_t)B_ * OT_ * H_ / 4;
        emb_all_k<<<(unsigned)((total4 + TPB - 1) / TPB), TPB>>>(opc, var, out_emb);
    }
}

// round 7
// speedup vs baseline: 8.0649x; 1.8632x over previous
#include <cuda_runtime.h>
#include <cuda_fp16.h>
#include <math.h>
#include <stdint.h>

#define B_   256
#define S1_  512
#define S2_  64
#define H_   768
#define OPC_ 64
#define OT_  128
#define NEGV (-1e12f)

// ---------------- scratch (device globals) ----------------------------------
__device__ float g_gAB [B_ * 2 * H_];     // [B][1536]: cols 0-767 = gA, 768+ = gB
__device__ float g_gCD [B_ * 2 * H_];     // [B][1536]: gC | gD
__device__ float g_node[B_ * H_];
__device__ float g_P1  [B_ * H_];
__device__ float g_eng [B_ * S1_];
__device__ float g_ctx [B_ * H_];
__device__ float g_Q1  [B_ * H_];
__device__ float g_Q2c [OPC_ * H_];
// fp16 activations (MMA A-operands)
__device__ __half g_encH [(size_t)B_ * S1_ * H_];
__device__ __half g_varH [(size_t)B_ * S2_ * H_];
__device__ __half g_curH [B_ * H_];
__device__ __half g_opcH [OPC_ * H_];
__device__ __half g_lcH  [B_ * 2 * H_];
__device__ __half g_nodeH[B_ * H_];
__device__ __half g_leafH[B_ * 2 * H_];
// fp16 transposed weights: Wt[n][k] = W[k][n]
__device__ __half g_WtLLG [2 * H_ * H_];      // [1536 n][768 k]  (W_l | W_lg)
__device__ __half g_WtRRG [2 * H_ * 2 * H_];  // [1536 n][1536 k] (W_r | W_rg)
__device__ __half g_WtA1  [H_ * H_];
__device__ __half g_WtA2  [H_ * H_];
__device__ __half g_WtS3  [H_ * H_];
__device__ __half g_WtS12 [H_ * 2 * H_];      // [768 n][1536 k]

// ---------------- helpers ------------------------------------------------------
__device__ __forceinline__ float tanh_fast(float x) {
    float y; asm("tanh.approx.f32 %0, %1;" : "=f"(y) : "f"(x)); return y;
}
__device__ __forceinline__ float ftanh(float x) {
    float ax = fabsf(x);
    float e  = __expf(2.0f * ax);
    float r  = 1.0f - __fdividef(2.0f, e + 1.0f);
    return copysignf(r, x);
}
__device__ __forceinline__ float fsig(float x) {
    return __fdividef(1.0f, 1.0f + __expf(-x));
}
__device__ __forceinline__ uint32_t smem_u32(const void* p) {
    uint32_t a;
    asm("{ .reg .u64 t; cvta.to.shared.u64 t, %1; cvt.u32.u64 %0, t; }" : "=r"(a) : "l"(p));
    return a;
}
__device__ __forceinline__ void cp16(uint32_t saddr, const __half* g, uint32_t sz) {
    asm volatile("cp.async.cg.shared.global [%0], [%1], 16, %2;"
                 :: "r"(saddr), "l"(g), "r"(sz) : "memory");
}
__device__ __forceinline__ void cp_commit() {
    asm volatile("cp.async.commit_group;" ::: "memory");
}
__device__ __forceinline__ void cp_wait2() {
    asm volatile("cp.async.wait_group 2;" ::: "memory");
}
__device__ __forceinline__ void ldm4(uint32_t r[4], uint32_t addr) {
    asm volatile("ldmatrix.sync.aligned.m8n8.x4.shared.b16 {%0,%1,%2,%3}, [%4];"
                 : "=r"(r[0]), "=r"(r[1]), "=r"(r[2]), "=r"(r[3]) : "r"(addr));
}
__device__ __forceinline__ void mma_f16(float c[4], const uint32_t a[4],
                                        uint32_t b0, uint32_t b1) {
    asm volatile(
        "mma.sync.aligned.m16n8k16.row.col.f32.f16.f16.f32 "
        "{%0,%1,%2,%3}, {%4,%5,%6,%7}, {%8,%9}, {%0,%1,%2,%3};"
        : "+f"(c[0]), "+f"(c[1]), "+f"(c[2]), "+f"(c[3])
        : "r"(a[0]), "r"(a[1]), "r"(a[2]), "r"(a[3]), "r"(b0), "r"(b1));
}

// ---------------- pipelined fp16 MMA kernel (cp.async 4-stage, BK=32) ----------
// C-tile 128m x 128n, 256 thr = 8 warps (4 m-bands x 2 n-halves), warp 32x64.
// A row-major [M,K] fp16; Wt row-major [N][K] fp16. SMEM rows padded to 40 halfs.
// MODE 0: split-K (blockIdx.z), atomicAdd into C[M,ldc] (bias preloaded).
// MODE 1: energy out[r] += sum_n v[n]*tanh(aux1[bm>>9, n] + acc)
// MODE 2: score  out[(r>>6)*128+64+(r&63)] += sum_n v[n]*tanh(aux1[r>>6, n] + acc)
#define KPAD 40
#define STAGE_BYTES (128 * KPAD * 2)        // 10240 B per operand per stage
#define SMEM_MMA (8 * STAGE_BYTES)          // 4 stages x (A+B) = 81920 B

template <int MODE>
__global__ __launch_bounds__(256, 2) void mma_k(
    const __half* __restrict__ A, const __half* __restrict__ Wt,
    float* __restrict__ outv,
    const float* __restrict__ aux1, const float* __restrict__ aux2,
    int M, int K, int niter, int ldc)
{
    extern __shared__ __align__(16) __half smh[];
    const uint32_t sA = smem_u32(smh);
    const uint32_t sB = sA + 4 * STAGE_BYTES;

    const int tid  = threadIdx.x;
    const int lane = tid & 31;
    const int wid  = tid >> 5;
    const int wm   = wid & 3;
    const int wn   = wid >> 2;
    const int bm   = blockIdx.y * 128;
    const int bn   = blockIdx.x * 128;
    const int kst  = blockIdx.z * niter * 32;

    float acc[2][8][4];
#pragma unroll
    for (int i = 0; i < 2; i++)
#pragma unroll
        for (int j = 0; j < 8; j++)
#pragma unroll
            for (int q = 0; q < 4; q++) acc[i][j][q] = 0.f;

    // loaders: 2 threads per row, 32B each (BK=32 halfs = 64B/row)
    const int l_row = tid >> 1;
    const int lq    = tid & 1;
    const uint32_t a_sz = ((bm + l_row) < M) ? 16u : 0u;
    const __half* Ap = A  + (size_t)(bm + l_row) * K + kst + lq * 16;
    const __half* Bp = Wt + (size_t)(bn + l_row) * K + kst + lq * 16;
    const uint32_t dA = sA + (uint32_t)(l_row * KPAD + lq * 16) * 2u;
    const uint32_t dB = sB + (uint32_t)(l_row * KPAD + lq * 16) * 2u;

    auto issue = [&](int stage, int kt) {
        const __half* a = Ap + (size_t)kt * 32;
        const __half* b = Bp + (size_t)kt * 32;
        uint32_t so = (uint32_t)stage * STAGE_BYTES;
        cp16(dA + so,      a,     a_sz);
        cp16(dA + so + 16, a + 8, a_sz);
        cp16(dB + so,      b,     16u);
        cp16(dB + so + 16, b + 8, 16u);
    };

#pragma unroll
    for (int s = 0; s < 3; s++) {
        if (s < niter) issue(s, s);
        cp_commit();
    }

    const int lk = lane & 3;
    const int lg = lane >> 2;
    const int l15 = lane & 15;
    const int lhi = lane >> 4;          // 0/1
    const int l8k = (lane >> 3) & 1;
    const int l7  = lane & 7;

    // ldmatrix base offsets (within a stage), k-part added per ks
    const uint32_t aoff = (uint32_t)((wm * 32 + l15) * KPAD) * 2u + (uint32_t)lhi * 16u;
    const uint32_t boff = (uint32_t)((wn * 64 + l7 + lhi * 8) * KPAD) * 2u + (uint32_t)l8k * 16u;

    for (int c = 0; c < niter; c++) {
        cp_wait2();
        __syncthreads();
        const uint32_t so = (uint32_t)(c & 3) * STAGE_BYTES;

#pragma unroll
        for (int ks = 0; ks < 2; ks++) {
            const uint32_t kso = (uint32_t)ks * 32u;
            uint32_t a0[4], a1[4];
            ldm4(a0, sA + so + aoff + kso);
            ldm4(a1, sA + so + aoff + kso + 16u * KPAD * 2u);
#pragma unroll
            for (int p = 0; p < 4; p++) {
                uint32_t bb[4];
                ldm4(bb, sB + so + boff + kso + (uint32_t)(p * 16 * KPAD) * 2u);
                mma_f16(acc[0][2 * p],     a0, bb[0], bb[1]);
                mma_f16(acc[0][2 * p + 1], a0, bb[2], bb[3]);
                mma_f16(acc[1][2 * p],     a1, bb[0], bb[1]);
                mma_f16(acc[1][2 * p + 1], a1, bb[2], bb[3]);
            }
        }

        if (c + 3 < niter) issue((c + 3) & 3, c + 3);
        cp_commit();
    }

    // ---------------- epilogues ----------------
    if (MODE == 0) {
#pragma unroll
        for (int ti = 0; ti < 2; ti++)
#pragma unroll
            for (int nj = 0; nj < 8; nj++) {
                int r0 = bm + wm * 32 + ti * 16 + lg;
                int cc = bn + wn * 64 + nj * 8 + 2 * lk;
                if (r0 < M) {
                    atomicAdd(&outv[(size_t)r0 * ldc + cc],     acc[ti][nj][0]);
                    atomicAdd(&outv[(size_t)r0 * ldc + cc + 1], acc[ti][nj][1]);
                }
                if (r0 + 8 < M) {
                    atomicAdd(&outv[(size_t)(r0 + 8) * ldc + cc],     acc[ti][nj][2]);
                    atomicAdd(&outv[(size_t)(r0 + 8) * ldc + cc + 1], acc[ti][nj][3]);
                }
            }
        return;
    }

    float vv[16];
#pragma unroll
    for (int nj = 0; nj < 8; nj++)
#pragma unroll
        for (int u = 0; u < 2; u++)
            vv[nj * 2 + u] = __ldg(&aux2[bn + wn * 64 + nj * 8 + 2 * lk + u]);

    if (MODE == 1) {
        const int b = bm >> 9;
        float p1v[16];
#pragma unroll
        for (int nj = 0; nj < 8; nj++)
#pragma unroll
            for (int u = 0; u < 2; u++)
                p1v[nj * 2 + u] = __ldg(&aux1[(size_t)b * H_ + bn + wn * 64 + nj * 8 + 2 * lk + u]);
#pragma unroll
        for (int ti = 0; ti < 2; ti++)
#pragma unroll
            for (int half = 0; half < 2; half++) {
                int r = bm + wm * 32 + ti * 16 + lg + half * 8;
                float part = 0.f;
#pragma unroll
                for (int nj = 0; nj < 8; nj++) {
                    part += vv[nj * 2]     * tanh_fast(acc[ti][nj][half * 2]     + p1v[nj * 2]);
                    part += vv[nj * 2 + 1] * tanh_fast(acc[ti][nj][half * 2 + 1] + p1v[nj * 2 + 1]);
                }
                part += __shfl_xor_sync(0xFFFFFFFFu, part, 1);
                part += __shfl_xor_sync(0xFFFFFFFFu, part, 2);
                if (lk == 0) atomicAdd(&outv[r], part);
            }
    } else {
#pragma unroll
        for (int ti = 0; ti < 2; ti++)
#pragma unroll
            for (int half = 0; half < 2; half++) {
                int r = bm + wm * 32 + ti * 16 + lg + half * 8;
                int b = r >> 6;
                const float* q1 = aux1 + (size_t)b * H_;
                float part = 0.f;
#pragma unroll
                for (int nj = 0; nj < 8; nj++) {
                    int n = bn + wn * 64 + nj * 8 + 2 * lk;
                    part += vv[nj * 2]     * tanh_fast(acc[ti][nj][half * 2]     + __ldg(&q1[n]));
                    part += vv[nj * 2 + 1] * tanh_fast(acc[ti][nj][half * 2 + 1] + __ldg(&q1[n + 1]));
                }
                part += __shfl_xor_sync(0xFFFFFFFFu, part, 1);
                part += __shfl_xor_sync(0xFFFFFFFFu, part, 2);
                if (lk == 0) atomicAdd(&outv[(size_t)b * OT_ + OPC_ + (r & 63)], part);
            }
    }
}

// ---------------- small helpers ----------------------------------------------
__global__ void fill_mega_k(
    float* gAB, const float* bA, const float* bB,
    float* gCD, const float* bC, const float* bD,
    float* P1, const float* bE, float* Q1, const float* bF,
    float* z1, int n1, float* z2, int n2, float* z3, int n3)
{
    const int BH = B_ * H_;
    const int BH2 = B_ * 2 * H_;
    int i = blockIdx.x * blockDim.x + threadIdx.x;
    if (i < BH2) {
        int h = i % (2 * H_);
        gAB[i] = (h < H_) ? bA[h] : bB[h - H_];
        return;
    }
    i -= BH2;
    if (i < BH2) {
        int h = i % (2 * H_);
        gCD[i] = (h < H_) ? bC[h] : bD[h - H_];
        return;
    }
    i -= BH2;
    if (i < BH) { P1[i] = bE[i % H_]; return; }
    i -= BH;
    if (i < BH) { Q1[i] = bF[i % H_]; return; }
    i -= BH;
    if (i < n1) { z1[i] = 0.f; return; }
    i -= n1;
    if (i < n2) { z2[i] = 0.f; return; }
    i -= n2;
    if (i < n3) z3[i] = 0.f;
}

__global__ void cvt_h_k(const float* __restrict__ src, __half* __restrict__ dst, int n4)
{
    int i = blockIdx.x * blockDim.x + threadIdx.x;
    if (i >= n4) return;
    float4 v = ((const float4*)src)[i];
    __half2 h0 = __floats2half2_rn(v.x, v.y);
    __half2 h1 = __floats2half2_rn(v.z, v.w);
    ((__half2*)dst)[2 * i]     = h0;
    ((__half2*)dst)[2 * i + 1] = h1;
}

// batched 768x768 transposes -> fp16; dst row stride = 768
__global__ void transpose5h_k(const float* s0, __half* d0, const float* s1, __half* d1,
                              const float* s2, __half* d2, const float* s3, __half* d3,
                              const float* s4, __half* d4)
{
    __shared__ float t[32][33];
    const float* src; __half* dst;
    switch (blockIdx.z) {
        case 0: src = s0; dst = d0; break;
        case 1: src = s1; dst = d1; break;
        case 2: src = s2; dst = d2; break;
        case 3: src = s3; dst = d3; break;
        default: src = s4; dst = d4; break;
    }
    int bx = blockIdx.x * 32, by = blockIdx.y * 32;
    int x = threadIdx.x, y = threadIdx.y;
#pragma unroll
    for (int i = 0; i < 32; i += 8)
        t[y + i][x] = src[(size_t)(by + y + i) * H_ + bx + x];
    __syncthreads();
#pragma unroll
    for (int i = 0; i < 32; i += 8)
        dst[(size_t)(bx + y + i) * H_ + by + x] = __float2half_rn(t[x][y + i]);
}

// batched [1536][768] transposes -> fp16 [768 n][1536 k]
__global__ void transpose3h_k(const float* s0, __half* d0, const float* s1, __half* d1,
                              const float* s2, __half* d2)
{
    __shared__ float t[32][33];
    const float* src; __half* dst;
    switch (blockIdx.z) {
        case 0: src = s0; dst = d0; break;
        case 1: src = s1; dst = d1; break;
        default: src = s2; dst = d2; break;
    }
    int bx = blockIdx.x * 32, by = blockIdx.y * 32;   // grid (24, 48)
    int x = threadIdx.x, y = threadIdx.y;
#pragma unroll
    for (int i = 0; i < 32; i += 8)
        t[y + i][x] = src[(size_t)(by + y + i) * H_ + bx + x];
    __syncthreads();
#pragma unroll
    for (int i = 0; i < 32; i += 8)
        dst[(size_t)(bx + y + i) * (2 * H_) + by + x] = __float2half_rn(t[x][y + i]);
}

__global__ void concat2h_k(const float* __restrict__ x, const float* __restrict__ y,
                           __half* __restrict__ out)
{
    int i = blockIdx.x * blockDim.x + threadIdx.x;
    if (i >= B_ * H_) return;
    int b = i / H_, h = i % H_;
    out[(size_t)b * 2 * H_ + h]      = __float2half_rn(x[i]);
    out[(size_t)b * 2 * H_ + H_ + h] = __float2half_rn(y[i]);
}

__global__ void combine_node_k(const int* __restrict__ has_left,
                               float* __restrict__ out_node)
{
    int i = blockIdx.x * blockDim.x + threadIdx.x;
    if (i >= B_ * H_) return;
    int b = i / H_, h = i % H_;
    size_t base = (size_t)b * 2 * H_ + h;
    float v = has_left[b] ? ftanh(g_gCD[base]) * fsig(g_gCD[base + H_])
                          : ftanh(g_gAB[base]) * fsig(g_gAB[base + H_]);
    g_node[i] = v;
    g_nodeH[i] = __float2half_rn(v);
    out_node[i] = v;
}

__global__ void softmax_k(const int* __restrict__ smask)
{
    __shared__ float red[256];
    int b = blockIdx.x, t = threadIdx.x;
    float* e = g_eng + (size_t)b * S1_;
    const int* m = smask + (size_t)b * S1_;
    float x0 = m[t]       ? NEGV : e[t];
    float x1 = m[t + 256] ? NEGV : e[t + 256];
    red[t] = fmaxf(x0, x1);
    __syncthreads();
    for (int s = 128; s > 0; s >>= 1) {
        if (t < s) red[t] = fmaxf(red[t], red[t + s]);
        __syncthreads();
    }
    float mx = red[0];
    __syncthreads();
    float e0 = __expf(x0 - mx), e1 = __expf(x1 - mx);
    red[t] = e0 + e1;
    __syncthreads();
    for (int s = 128; s > 0; s >>= 1) {
        if (t < s) red[t] += red[t + s];
        __syncthreads();
    }
    float inv = __fdividef(1.f, red[0]);
    e[t] = e0 * inv;
    e[t + 256] = e1 * inv;
}

__global__ void context_k(const float* __restrict__ enc, float* __restrict__ out_ctx)
{
    int b = blockIdx.x, h = threadIdx.x;
    const float* a = g_eng + (size_t)b * S1_;
    const float* e = enc + (size_t)b * S1_ * H_ + h;
    float acc = 0.f;
#pragma unroll 8
    for (int s = 0; s < S1_; s++)
        acc = fmaf(__ldg(a + s), __ldg(e + (size_t)s * H_), acc);
    g_ctx[(size_t)b * H_ + h] = acc;
    out_ctx[(size_t)b * H_ + h] = acc;
}

__global__ void finalize_score_k(const float* __restrict__ vsc,
                                 const int* __restrict__ cmask,
                                 float* __restrict__ score)
{
    int idx = (blockIdx.x * blockDim.x + threadIdx.x) >> 5;
    if (idx >= B_ * OT_) return;
    int lane = threadIdx.x & 31;
    int b = idx >> 7, o = idx & 127;
    if (cmask[idx]) {
        if (lane == 0) score[idx] = NEGV;
        return;
    }
    if (o >= OPC_) return;
    const float* q1 = g_Q1 + (size_t)b * H_;
    const float* q2 = g_Q2c + (size_t)o * H_;
    float acc = 0.f;
    for (int h = lane; h < H_; h += 32)
        acc += vsc[h] * ftanh(q1[h] + q2[h]);
#pragma unroll
    for (int off = 16; off; off >>= 1) acc += __shfl_xor_sync(0xFFFFFFFFu, acc, off);
    if (lane == 0) score[idx] = acc;
}

__global__ void emb_all_k(const float* __restrict__ opc, const float* __restrict__ var,
                          float* __restrict__ dst)
{
    size_t i = (size_t)blockIdx.x * blockDim.x + threadIdx.x;
    const size_t total = (size_t)B_ * OT_ * H_ / 4;
    if (i >= total) return;
    size_t elem = i * 4;
    int h = (int)(elem % H_);
    size_t bo = elem / H_;
    int o = (int)(bo % OT_);
    int b = (int)(bo / OT_);
    float4 v;
    if (o < OPC_) v = *(const float4*)(opc + (size_t)o * H_ + h);
    else          v = *(const float4*)(var + ((size_t)b * S2_ + (o - OPC_)) * H_ + h);
    ((float4*)dst)[i] = v;
}

// ---------------- launch -------------------------------------------------------
extern "C" void kernel_launch(void* const* d_in, const int* in_sizes, int n_in,
                              void* d_out, int out_size)
{
    (void)in_sizes; (void)n_in; (void)out_size;
    const float* current = (const float*)d_in[0];
    const float* left    = (const float*)d_in[1];
    const float* enc     = (const float*)d_in[2];
    const float* var     = (const float*)d_in[3];
    const float* opc     = (const float*)d_in[4];
    const float* W_l     = (const float*)d_in[5];
    const float* b_l     = (const float*)d_in[6];
    const float* W_lg    = (const float*)d_in[7];
    const float* b_lg    = (const float*)d_in[8];
    const float* W_r     = (const float*)d_in[9];
    const float* b_r     = (const float*)d_in[10];
    const float* W_rg    = (const float*)d_in[11];
    const float* b_rg    = (const float*)d_in[12];
    const float* W_attn  = (const float*)d_in[13];
    const float* b_attn  = (const float*)d_in[14];
    const float* v_attn  = (const float*)d_in[15];
    const float* W_score = (const float*)d_in[16];
    const float* b_score = (const float*)d_in[17];
    const float* v_score = (const float*)d_in[18];
    const int*   has_left = (const int*)d_in[19];
    const int*   smask    = (const int*)d_in[20];
    const int*   cmask    = (const int*)d_in[21];

    float *gAB, *gCD, *node, *P1, *eng, *ctx, *Q1, *Q2c;
    __half *encH, *varH, *curH, *opcH, *lcH, *nodeH, *leafH;
    __half *WtLLG, *WtRRG, *WtA1, *WtA2, *WtS3, *WtS12;
    cudaGetSymbolAddress((void**)&gAB,  g_gAB);
    cudaGetSymbolAddress((void**)&gCD,  g_gCD);
    cudaGetSymbolAddress((void**)&node, g_node);
    cudaGetSymbolAddress((void**)&P1,   g_P1);
    cudaGetSymbolAddress((void**)&eng,  g_eng);
    cudaGetSymbolAddress((void**)&ctx,  g_ctx);
    cudaGetSymbolAddress((void**)&Q1,   g_Q1);
    cudaGetSymbolAddress((void**)&Q2c,  g_Q2c);
    cudaGetSymbolAddress((void**)&encH, g_encH);
    cudaGetSymbolAddress((void**)&varH, g_varH);
    cudaGetSymbolAddress((void**)&curH, g_curH);
    cudaGetSymbolAddress((void**)&opcH, g_opcH);
    cudaGetSymbolAddress((void**)&lcH,  g_lcH);
    cudaGetSymbolAddress((void**)&nodeH, g_nodeH);
    cudaGetSymbolAddress((void**)&leafH, g_leafH);
    cudaGetSymbolAddress((void**)&WtLLG, g_WtLLG);
    cudaGetSymbolAddress((void**)&WtRRG, g_WtRRG);
    cudaGetSymbolAddress((void**)&WtA1, g_WtA1);
    cudaGetSymbolAddress((void**)&WtA2, g_WtA2);
    cudaGetSymbolAddress((void**)&WtS3, g_WtS3);
    cudaGetSymbolAddress((void**)&WtS12, g_WtS12);

    float* out       = (float*)d_out;
    float* out_score = out;
    float* out_node  = out_score + B_ * OT_;
    float* out_ctx   = out_node + B_ * H_;
    float* out_emb   = out_ctx + B_ * H_;

    const int BH = B_ * H_;
    const int TPB = 256;

    cudaFuncSetAttribute(mma_k<0>, cudaFuncAttributeMaxDynamicSharedMemorySize, SMEM_MMA);
    cudaFuncSetAttribute(mma_k<1>, cudaFuncAttributeMaxDynamicSharedMemorySize, SMEM_MMA);
    cudaFuncSetAttribute(mma_k<2>, cudaFuncAttributeMaxDynamicSharedMemorySize, SMEM_MMA);

    // --- fills + conversions + transposes (independent) ---
    {
        int total = 2 * (B_ * 2 * H_) + 2 * BH + B_ * S1_ + B_ * OT_ + OPC_ * H_;
        fill_mega_k<<<(total + TPB - 1) / TPB, TPB>>>(
            gAB, b_l, b_lg, gCD, b_r, b_rg, P1, b_attn, Q1, b_score,
            eng, B_ * S1_, out_score, B_ * OT_, Q2c, OPC_ * H_);
    }
    cvt_h_k<<<(BH / 4 + TPB - 1) / TPB, TPB>>>(current, curH, BH / 4);
    cvt_h_k<<<(OPC_ * H_ / 4 + TPB - 1) / TPB, TPB>>>(opc, opcH, OPC_ * H_ / 4);
    cvt_h_k<<<(B_ * S2_ * H_ / 4 + TPB - 1) / TPB, TPB>>>(var, varH, B_ * S2_ * H_ / 4);
    {
        int n4 = B_ * S1_ * (H_ / 4);
        cvt_h_k<<<(n4 + TPB - 1) / TPB, TPB>>>(enc, encH, n4);
    }
    transpose5h_k<<<dim3(24, 24, 5), dim3(32, 8)>>>(
        W_l, WtLLG, W_lg, WtLLG + (size_t)H_ * H_,
        W_attn, WtA1, W_attn + (size_t)H_ * H_, WtA2,
        W_score + (size_t)2 * H_ * H_, WtS3);
    transpose3h_k<<<dim3(24, 48, 3), dim3(32, 8)>>>(
        W_r, WtRRG, W_rg, WtRRG + (size_t)H_ * 2 * H_, W_score, WtS12);
    concat2h_k<<<(BH + TPB - 1) / TPB, TPB>>>(left, current, lcH);

    // --- node: two merged gate GEMMs ---
    mma_k<0><<<dim3(12, 2, 6),  256, SMEM_MMA>>>(curH, WtLLG, gAB, nullptr, nullptr,
                                                 B_, H_, 4, 2 * H_);
    mma_k<0><<<dim3(12, 2, 12), 256, SMEM_MMA>>>(lcH, WtRRG, gCD, nullptr, nullptr,
                                                 B_, 2 * H_, 4, 2 * H_);
    combine_node_k<<<(BH + TPB - 1) / TPB, TPB>>>(has_left, out_node);

    // --- attention ---
    mma_k<0><<<dim3(6, 2, 6), 256, SMEM_MMA>>>(nodeH, WtA1, P1, nullptr, nullptr,
                                               B_, H_, 4, H_);
    mma_k<1><<<dim3(6, (B_ * S1_) / 128, 1), 256, SMEM_MMA>>>(encH, WtA2, eng, P1, v_attn,
                                                              B_ * S1_, H_, 24, 0);
    softmax_k<<<B_, 256>>>(smask);
    context_k<<<B_, H_>>>(enc, out_ctx);

    // --- leaf score ---
    concat2h_k<<<(BH + TPB - 1) / TPB, TPB>>>(node, ctx, leafH);
    mma_k<0><<<dim3(6, 2, 12), 256, SMEM_MMA>>>(leafH, WtS12, Q1, nullptr, nullptr,
                                                B_, 2 * H_, 4, H_);
    mma_k<0><<<dim3(6, 1, 6),  256, SMEM_MMA>>>(opcH, WtS3, Q2c, nullptr, nullptr,
                                                OPC_, H_, 4, H_);
    mma_k<2><<<dim3(6, (B_ * S2_) / 128, 1), 256, SMEM_MMA>>>(varH, WtS3, out_score, Q1, v_score,
                                                              B_ * S2_, H_, 24, 0);
    finalize_score_k<<<(B_ * OT_ * 32 + TPB - 1) / TPB, TPB>>>(v_score, cmask, out_score);

    // --- emb_all output (exact fp32 copies) ---
    {
        size_t total4 = (size_t)B_ * OT_ * H_ / 4;
        emb_all_k<<<(unsigned)((total4 + TPB - 1) / TPB), TPB>>>(opc, var, out_emb);
    }
}

// round 8
// speedup vs baseline: 9.1775x; 1.1380x over previous
#include <cuda_runtime.h>
#include <cuda_fp16.h>
#include <math.h>
#include <stdint.h>

#define B_   256
#define S1_  512
#define S2_  64
#define H_   768
#define OPC_ 64
#define OT_  128
#define NEGV (-1e12f)

// ---------------- scratch (device globals) ----------------------------------
__device__ float g_gAB [B_ * 2 * H_];     // [B][1536]: gA | gB
__device__ float g_gCD [B_ * 2 * H_];     // [B][1536]: gC | gD
__device__ float g_node[B_ * H_];
__device__ float g_P1  [B_ * H_];
__device__ float g_eng [B_ * S1_];
__device__ float g_ctx [B_ * H_];
__device__ float g_Q1  [B_ * H_];
__device__ float g_Q2c [OPC_ * H_];
// fp16 activations
__device__ __half g_encH [(size_t)B_ * S1_ * H_];
__device__ __half g_varH [(size_t)B_ * S2_ * H_];
__device__ __half g_curH [B_ * H_];
__device__ __half g_opcH [OPC_ * H_];
__device__ __half g_lcH  [B_ * 2 * H_];
__device__ __half g_nodeH[B_ * H_];
__device__ __half g_leafH[B_ * 2 * H_];
// fp16 transposed weights: Wt[n][k] = W[k][n]
__device__ __half g_WtLLG [2 * H_ * H_];
__device__ __half g_WtRRG [2 * H_ * 2 * H_];
__device__ __half g_WtA1  [H_ * H_];
__device__ __half g_WtA2  [H_ * H_];
__device__ __half g_WtS3  [H_ * H_];
__device__ __half g_WtS12 [H_ * 2 * H_];

// ---------------- helpers ------------------------------------------------------
__device__ __forceinline__ float tanh_fast(float x) {
    float y; asm("tanh.approx.f32 %0, %1;" : "=f"(y) : "f"(x)); return y;
}
__device__ __forceinline__ float ftanh(float x) {
    float ax = fabsf(x);
    float e  = __expf(2.0f * ax);
    float r  = 1.0f - __fdividef(2.0f, e + 1.0f);
    return copysignf(r, x);
}
__device__ __forceinline__ float fsig(float x) {
    return __fdividef(1.0f, 1.0f + __expf(-x));
}
__device__ __forceinline__ uint32_t smem_u32(const void* p) {
    uint32_t a;
    asm("{ .reg .u64 t; cvta.to.shared.u64 t, %1; cvt.u32.u64 %0, t; }" : "=r"(a) : "l"(p));
    return a;
}
__device__ __forceinline__ void cp16(uint32_t saddr, const __half* g, uint32_t sz) {
    asm volatile("cp.async.cg.shared.global [%0], [%1], 16, %2;"
                 :: "r"(saddr), "l"(g), "r"(sz) : "memory");
}
__device__ __forceinline__ void cp_commit() {
    asm volatile("cp.async.commit_group;" ::: "memory");
}
__device__ __forceinline__ void cp_wait2() {
    asm volatile("cp.async.wait_group 2;" ::: "memory");
}
__device__ __forceinline__ void ldm4(uint32_t r[4], uint32_t addr) {
    asm volatile("ldmatrix.sync.aligned.m8n8.x4.shared.b16 {%0,%1,%2,%3}, [%4];"
                 : "=r"(r[0]), "=r"(r[1]), "=r"(r[2]), "=r"(r[3]) : "r"(addr));
}
__device__ __forceinline__ void mma_f16(float c[4], const uint32_t a[4],
                                        uint32_t b0, uint32_t b1) {
    asm volatile(
        "mma.sync.aligned.m16n8k16.row.col.f32.f16.f16.f32 "
        "{%0,%1,%2,%3}, {%4,%5,%6,%7}, {%8,%9}, {%0,%1,%2,%3};"
        : "+f"(c[0]), "+f"(c[1]), "+f"(c[2]), "+f"(c[3])
        : "r"(a[0]), "r"(a[1]), "r"(a[2]), "r"(a[3]), "r"(b0), "r"(b1));
}

// ---------------- pipelined fp16 MMA kernel (cp.async 4-stage, BK=32) ----------
// C-tile 128m x 256n, 512 thr = 16 warps (4 m-bands x 4 n-groups), warp 32x64.
// A row-major [M,K] fp16; Wt row-major [N][K] fp16. SMEM rows padded to 40 halfs.
// MODE 0: split-K (blockIdx.z), atomicAdd into C[M,ldc] (bias preloaded).
// MODE 1: energy out[r] += sum_n v[n]*tanh(aux1[bm>>9, n] + acc)
// MODE 2: score  out[(r>>6)*128+64+(r&63)] += sum_n v[n]*tanh(aux1[r>>6, n] + acc)
#define KPAD 40
#define A_STAGE (128 * KPAD * 2)            // 10240 B
#define B_STAGE (256 * KPAD * 2)            // 20480 B
#define SMEM_MMA (4 * (A_STAGE + B_STAGE))  // 122880 B

template <int MODE>
__global__ __launch_bounds__(512, 1) void mma_k(
    const __half* __restrict__ A, const __half* __restrict__ Wt,
    float* __restrict__ outv,
    const float* __restrict__ aux1, const float* __restrict__ aux2,
    int M, int K, int niter, int ldc)
{
    extern __shared__ __align__(16) __half smh[];
    const uint32_t sA = smem_u32(smh);
    const uint32_t sB = sA + 4 * A_STAGE;

    const int tid  = threadIdx.x;
    const int lane = tid & 31;
    const int wid  = tid >> 5;
    const int wm   = wid & 3;           // m band (32 rows)
    const int wn   = wid >> 2;          // n group (64 cols), 0..3
    const int bm   = blockIdx.y * 128;
    const int bn   = blockIdx.x * 256;
    const int kst  = blockIdx.z * niter * 32;

    float acc[2][8][4];
#pragma unroll
    for (int i = 0; i < 2; i++)
#pragma unroll
        for (int j = 0; j < 8; j++)
#pragma unroll
            for (int q = 0; q < 4; q++) acc[i][j][q] = 0.f;

    // loaders: A 128 rows x 64B (1 cp16/thread); B 256 rows x 64B (2 cp16/thread)
    const int l_row = tid >> 2;
    const int lq    = tid & 3;
    const uint32_t a_sz = ((bm + l_row) < M) ? 16u : 0u;
    const __half* Ap  = A  + (size_t)(bm + l_row) * K + kst + lq * 8;
    const __half* Bp0 = Wt + (size_t)(bn + l_row) * K + kst + lq * 8;
    const __half* Bp1 = Wt + (size_t)(bn + 128 + l_row) * K + kst + lq * 8;
    const uint32_t dA  = sA + (uint32_t)(l_row * KPAD + lq * 8) * 2u;
    const uint32_t dB0 = sB + (uint32_t)(l_row * KPAD + lq * 8) * 2u;
    const uint32_t dB1 = sB + (uint32_t)((128 + l_row) * KPAD + lq * 8) * 2u;

    auto issue = [&](int stage, int kt) {
        cp16(dA  + (uint32_t)stage * A_STAGE, Ap  + (size_t)kt * 32, a_sz);
        cp16(dB0 + (uint32_t)stage * B_STAGE, Bp0 + (size_t)kt * 32, 16u);
        cp16(dB1 + (uint32_t)stage * B_STAGE, Bp1 + (size_t)kt * 32, 16u);
    };

#pragma unroll
    for (int s = 0; s < 3; s++) {
        if (s < niter) issue(s, s);
        cp_commit();
    }

    const int lk = lane & 3;
    const int lg = lane >> 2;
    const int l15 = lane & 15;
    const int lhi = lane >> 4;
    const int l8k = (lane >> 3) & 1;
    const int l7  = lane & 7;

    const uint32_t aoff = (uint32_t)((wm * 32 + l15) * KPAD) * 2u + (uint32_t)lhi * 16u;
    const uint32_t boff = (uint32_t)((wn * 64 + l7 + lhi * 8) * KPAD) * 2u + (uint32_t)l8k * 16u;

    for (int c = 0; c < niter; c++) {
        cp_wait2();
        __syncthreads();
        const uint32_t soa = (uint32_t)(c & 3) * A_STAGE;
        const uint32_t sob = (uint32_t)(c & 3) * B_STAGE;

#pragma unroll
        for (int ks = 0; ks < 2; ks++) {
            const uint32_t kso = (uint32_t)ks * 32u;
            uint32_t a0[4], a1[4];
            ldm4(a0, sA + soa + aoff + kso);
            ldm4(a1, sA + soa + aoff + kso + 16u * KPAD * 2u);
#pragma unroll
            for (int p = 0; p < 4; p++) {
                uint32_t bb[4];
                ldm4(bb, sB + sob + boff + kso + (uint32_t)(p * 16 * KPAD) * 2u);
                mma_f16(acc[0][2 * p],     a0, bb[0], bb[1]);
                mma_f16(acc[0][2 * p + 1], a0, bb[2], bb[3]);
                mma_f16(acc[1][2 * p],     a1, bb[0], bb[1]);
                mma_f16(acc[1][2 * p + 1], a1, bb[2], bb[3]);
            }
        }

        if (c + 3 < niter) issue((c + 3) & 3, c + 3);
        cp_commit();
    }

    // ---------------- epilogues ----------------
    if (MODE == 0) {
#pragma unroll
        for (int ti = 0; ti < 2; ti++)
#pragma unroll
            for (int nj = 0; nj < 8; nj++) {
                int r0 = bm + wm * 32 + ti * 16 + lg;
                int cc = bn + wn * 64 + nj * 8 + 2 * lk;
                if (r0 < M) {
                    atomicAdd(&outv[(size_t)r0 * ldc + cc],     acc[ti][nj][0]);
                    atomicAdd(&outv[(size_t)r0 * ldc + cc + 1], acc[ti][nj][1]);
                }
                if (r0 + 8 < M) {
                    atomicAdd(&outv[(size_t)(r0 + 8) * ldc + cc],     acc[ti][nj][2]);
                    atomicAdd(&outv[(size_t)(r0 + 8) * ldc + cc + 1], acc[ti][nj][3]);
                }
            }
        return;
    }

    float vv[16];
#pragma unroll
    for (int nj = 0; nj < 8; nj++)
#pragma unroll
        for (int u = 0; u < 2; u++)
            vv[nj * 2 + u] = __ldg(&aux2[bn + wn * 64 + nj * 8 + 2 * lk + u]);

    if (MODE == 1) {
        const int b = bm >> 9;
        float p1v[16];
#pragma unroll
        for (int nj = 0; nj < 8; nj++)
#pragma unroll
            for (int u = 0; u < 2; u++)
                p1v[nj * 2 + u] = __ldg(&aux1[(size_t)b * H_ + bn + wn * 64 + nj * 8 + 2 * lk + u]);
#pragma unroll
        for (int ti = 0; ti < 2; ti++)
#pragma unroll
            for (int half = 0; half < 2; half++) {
                int r = bm + wm * 32 + ti * 16 + lg + half * 8;
                float part = 0.f;
#pragma unroll
                for (int nj = 0; nj < 8; nj++) {
                    part += vv[nj * 2]     * tanh_fast(acc[ti][nj][half * 2]     + p1v[nj * 2]);
                    part += vv[nj * 2 + 1] * tanh_fast(acc[ti][nj][half * 2 + 1] + p1v[nj * 2 + 1]);
                }
                part += __shfl_xor_sync(0xFFFFFFFFu, part, 1);
                part += __shfl_xor_sync(0xFFFFFFFFu, part, 2);
                if (lk == 0) atomicAdd(&outv[r], part);
            }
    } else {
#pragma unroll
        for (int ti = 0; ti < 2; ti++)
#pragma unroll
            for (int half = 0; half < 2; half++) {
                int r = bm + wm * 32 + ti * 16 + lg + half * 8;
                int b = r >> 6;
                const float* q1 = aux1 + (size_t)b * H_;
                float part = 0.f;
#pragma unroll
                for (int nj = 0; nj < 8; nj++) {
                    int n = bn + wn * 64 + nj * 8 + 2 * lk;
                    part += vv[nj * 2]     * tanh_fast(acc[ti][nj][half * 2]     + __ldg(&q1[n]));
                    part += vv[nj * 2 + 1] * tanh_fast(acc[ti][nj][half * 2 + 1] + __ldg(&q1[n + 1]));
                }
                part += __shfl_xor_sync(0xFFFFFFFFu, part, 1);
                part += __shfl_xor_sync(0xFFFFFFFFu, part, 2);
                if (lk == 0) atomicAdd(&outv[(size_t)b * OT_ + OPC_ + (r & 63)], part);
            }
    }
}

// ---------------- fused prep / epilogue helpers --------------------------------
__global__ void fill_mega_k(
    float* gAB, const float* bA, const float* bB,
    float* gCD, const float* bC, const float* bD,
    float* P1, const float* bE, float* Q1, const float* bF,
    float* z1, int n1, float* z2, int n2, float* z3, int n3)
{
    const int BH = B_ * H_;
    const int BH2 = B_ * 2 * H_;
    int i = blockIdx.x * blockDim.x + threadIdx.x;
    if (i < BH2) { int h = i % (2 * H_); gAB[i] = (h < H_) ? bA[h] : bB[h - H_]; return; }
    i -= BH2;
    if (i < BH2) { int h = i % (2 * H_); gCD[i] = (h < H_) ? bC[h] : bD[h - H_]; return; }
    i -= BH2;
    if (i < BH) { P1[i] = bE[i % H_]; return; }
    i -= BH;
    if (i < BH) { Q1[i] = bF[i % H_]; return; }
    i -= BH;
    if (i < n1) { z1[i] = 0.f; return; }
    i -= n1;
    if (i < n2) { z2[i] = 0.f; return; }
    i -= n2;
    if (i < n3) z3[i] = 0.f;
}

__global__ void cvt_h_k(const float* __restrict__ src, __half* __restrict__ dst, int n4)
{
    int i = blockIdx.x * blockDim.x + threadIdx.x;
    if (i >= n4) return;
    float4 v = ((const float4*)src)[i];
    ((__half2*)dst)[2 * i]     = __floats2half2_rn(v.x, v.y);
    ((__half2*)dst)[2 * i + 1] = __floats2half2_rn(v.z, v.w);
}

// current/left -> curH, lcH
__global__ void prep_cur_k(const float* __restrict__ current, const float* __restrict__ left,
                           __half* __restrict__ curH, __half* __restrict__ lcH)
{
    int i = blockIdx.x * blockDim.x + threadIdx.x;
    if (i >= B_ * H_) return;
    int b = i / H_, h = i % H_;
    float c = current[i], l = left[i];
    curH[i] = __float2half_rn(c);
    lcH[(size_t)b * 2 * H_ + h]      = __float2half_rn(l);
    lcH[(size_t)b * 2 * H_ + H_ + h] = __float2half_rn(c);
}

// opc/var -> out_emb (fp32) + opcH/varH (fp16), single pass
__global__ void prep_emb_k(const float* __restrict__ opc, const float* __restrict__ var,
                           float* __restrict__ out_emb,
                           __half* __restrict__ opcH, __half* __restrict__ varH)
{
    size_t i = (size_t)blockIdx.x * blockDim.x + threadIdx.x;   // float4 units
    const size_t total = (size_t)B_ * OT_ * (H_ / 4);
    if (i >= total) return;
    int h4 = (int)(i % (H_ / 4));
    size_t bo = i / (H_ / 4);
    int o = (int)(bo & 127);
    int b = (int)(bo >> 7);
    float4 v;
    if (o < OPC_) {
        size_t si = (size_t)o * (H_ / 4) + h4;
        v = ((const float4*)opc)[si];
        if (b == 0) {
            ((__half2*)opcH)[2 * si]     = __floats2half2_rn(v.x, v.y);
            ((__half2*)opcH)[2 * si + 1] = __floats2half2_rn(v.z, v.w);
        }
    } else {
        size_t si = ((size_t)b * S2_ + (o - OPC_)) * (H_ / 4) + h4;
        v = ((const float4*)var)[si];
        ((__half2*)varH)[2 * si]     = __floats2half2_rn(v.x, v.y);
        ((__half2*)varH)[2 * si + 1] = __floats2half2_rn(v.z, v.w);
    }
    ((float4*)out_emb)[i] = v;
}

// batched 768x768 transposes -> fp16
__global__ void transpose5h_k(const float* s0, __half* d0, const float* s1, __half* d1,
                              const float* s2, __half* d2, const float* s3, __half* d3,
                              const float* s4, __half* d4)
{
    __shared__ float t[32][33];
    const float* src; __half* dst;
    switch (blockIdx.z) {
        case 0: src = s0; dst = d0; break;
        case 1: src = s1; dst = d1; break;
        case 2: src = s2; dst = d2; break;
        case 3: src = s3; dst = d3; break;
        default: src = s4; dst = d4; break;
    }
    int bx = blockIdx.x * 32, by = blockIdx.y * 32;
    int x = threadIdx.x, y = threadIdx.y;
#pragma unroll
    for (int i = 0; i < 32; i += 8)
        t[y + i][x] = src[(size_t)(by + y + i) * H_ + bx + x];
    __syncthreads();
#pragma unroll
    for (int i = 0; i < 32; i += 8)
        dst[(size_t)(bx + y + i) * H_ + by + x] = __float2half_rn(t[x][y + i]);
}

// batched [1536][768] transposes -> fp16 [768 n][1536 k]
__global__ void transpose3h_k(const float* s0, __half* d0, const float* s1, __half* d1,
                              const float* s2, __half* d2)
{
    __shared__ float t[32][33];
    const float* src; __half* dst;
    switch (blockIdx.z) {
        case 0: src = s0; dst = d0; break;
        case 1: src = s1; dst = d1; break;
        default: src = s2; dst = d2; break;
    }
    int bx = blockIdx.x * 32, by = blockIdx.y * 32;   // grid (24, 48)
    int x = threadIdx.x, y = threadIdx.y;
#pragma unroll
    for (int i = 0; i < 32; i += 8)
        t[y + i][x] = src[(size_t)(by + y + i) * H_ + bx + x];
    __syncthreads();
#pragma unroll
    for (int i = 0; i < 32; i += 8)
        dst[(size_t)(bx + y + i) * (2 * H_) + by + x] = __float2half_rn(t[x][y + i]);
}

// gates -> node (fp32 + fp16 + output copy + lower half of leafH)
__global__ void combine_node_k(const int* __restrict__ has_left,
                               float* __restrict__ out_node)
{
    int i = blockIdx.x * blockDim.x + threadIdx.x;
    if (i >= B_ * H_) return;
    int b = i / H_, h = i % H_;
    size_t base = (size_t)b * 2 * H_ + h;
    float v = has_left[b] ? ftanh(g_gCD[base]) * fsig(g_gCD[base + H_])
                          : ftanh(g_gAB[base]) * fsig(g_gAB[base + H_]);
    g_node[i] = v;
    __half hv = __float2half_rn(v);
    g_nodeH[i] = hv;
    g_leafH[base] = hv;
    out_node[i] = v;
}

// fused softmax (over S1) + context (attn @ encH), per batch; writes ctx copies
// and the upper half of leafH. block = 768 threads, grid = B_.
__global__ __launch_bounds__(768) void softmax_context_k(
    const int* __restrict__ smask, const __half* __restrict__ encH,
    float* __restrict__ out_ctx)
{
    __shared__ float attn[S1_];
    __shared__ float wred[16];
    const int b = blockIdx.x, t = threadIdx.x;
    const int lane = t & 31, w = t >> 5;

    float x = 0.f;
    if (t < S1_)
        x = smask[(size_t)b * S1_ + t] ? NEGV : g_eng[(size_t)b * S1_ + t];

    // max reduce over first 512 threads
    if (t < S1_) {
        float m = x;
#pragma unroll
        for (int o = 16; o; o >>= 1) m = fmaxf(m, __shfl_xor_sync(0xFFFFFFFFu, m, o));
        if (lane == 0) wred[w] = m;
    }
    __syncthreads();
    if (t == 0) {
        float m = wred[0];
#pragma unroll
        for (int k = 1; k < 16; k++) m = fmaxf(m, wred[k]);
        wred[0] = m;
    }
    __syncthreads();
    const float mx = wred[0];
    __syncthreads();

    float e = 0.f;
    if (t < S1_) {
        e = __expf(x - mx);
        float s = e;
#pragma unroll
        for (int o = 16; o; o >>= 1) s += __shfl_xor_sync(0xFFFFFFFFu, s, o);
        if (lane == 0) wred[w] = s;
    }
    __syncthreads();
    if (t == 0) {
        float s = wred[0];
#pragma unroll
        for (int k = 1; k < 16; k++) s += wred[k];
        wred[0] = s;
    }
    __syncthreads();
    if (t < S1_) attn[t] = e * __fdividef(1.f, wred[0]);
    __syncthreads();

    // context: h = t (768 threads)
    const __half* ep = encH + (size_t)b * S1_ * H_ + t;
    float acc = 0.f;
#pragma unroll 8
    for (int s = 0; s < S1_; s++)
        acc = fmaf(attn[s], __half2float(ep[(size_t)s * H_]), acc);
    size_t oi = (size_t)b * H_ + t;
    g_ctx[oi] = acc;
    out_ctx[oi] = acc;
    g_leafH[(size_t)b * 2 * H_ + H_ + t] = __float2half_rn(acc);
}

__global__ void finalize_score_k(const float* __restrict__ vsc,
                                 const int* __restrict__ cmask,
                                 float* __restrict__ score)
{
    int idx = (blockIdx.x * blockDim.x + threadIdx.x) >> 5;
    if (idx >= B_ * OT_) return;
    int lane = threadIdx.x & 31;
    int b = idx >> 7, o = idx & 127;
    if (cmask[idx]) {
        if (lane == 0) score[idx] = NEGV;
        return;
    }
    if (o >= OPC_) return;
    const float* q1 = g_Q1 + (size_t)b * H_;
    const float* q2 = g_Q2c + (size_t)o * H_;
    float acc = 0.f;
    for (int h = lane; h < H_; h += 32)
        acc += vsc[h] * ftanh(q1[h] + q2[h]);
#pragma unroll
    for (int off = 16; off; off >>= 1) acc += __shfl_xor_sync(0xFFFFFFFFu, acc, off);
    if (lane == 0) score[idx] = acc;
}

// ---------------- launch -------------------------------------------------------
extern "C" void kernel_launch(void* const* d_in, const int* in_sizes, int n_in,
                              void* d_out, int out_size)
{
    (void)in_sizes; (void)n_in; (void)out_size;
    const float* current = (const float*)d_in[0];
    const float* left    = (const float*)d_in[1];
    const float* enc     = (const float*)d_in[2];
    const float* var     = (const float*)d_in[3];
    const float* opc     = (const float*)d_in[4];
    const float* W_l     = (const float*)d_in[5];
    const float* b_l     = (const float*)d_in[6];
    const float* W_lg    = (const float*)d_in[7];
    const float* b_lg    = (const float*)d_in[8];
    const float* W_r     = (const float*)d_in[9];
    const float* b_r     = (const float*)d_in[10];
    const float* W_rg    = (const float*)d_in[11];
    const float* b_rg    = (const float*)d_in[12];
    const float* W_attn  = (const float*)d_in[13];
    const float* b_attn  = (const float*)d_in[14];
    const float* v_attn  = (const float*)d_in[15];
    const float* W_score = (const float*)d_in[16];
    const float* b_score = (const float*)d_in[17];
    const float* v_score = (const float*)d_in[18];
    const int*   has_left = (const int*)d_in[19];
    const int*   smask    = (const int*)d_in[20];
    const int*   cmask    = (const int*)d_in[21];

    float *gAB, *gCD, *node, *P1, *eng, *ctx, *Q1, *Q2c;
    __half *encH, *varH, *curH, *opcH, *lcH, *nodeH, *leafH;
    __half *WtLLG, *WtRRG, *WtA1, *WtA2, *WtS3, *WtS12;
    cudaGetSymbolAddress((void**)&gAB,  g_gAB);
    cudaGetSymbolAddress((void**)&gCD,  g_gCD);
    cudaGetSymbolAddress((void**)&node, g_node);
    cudaGetSymbolAddress((void**)&P1,   g_P1);
    cudaGetSymbolAddress((void**)&eng,  g_eng);
    cudaGetSymbolAddress((void**)&ctx,  g_ctx);
    cudaGetSymbolAddress((void**)&Q1,   g_Q1);
    cudaGetSymbolAddress((void**)&Q2c,  g_Q2c);
    cudaGetSymbolAddress((void**)&encH, g_encH);
    cudaGetSymbolAddress((void**)&varH, g_varH);
    cudaGetSymbolAddress((void**)&curH, g_curH);
    cudaGetSymbolAddress((void**)&opcH, g_opcH);
    cudaGetSymbolAddress((void**)&lcH,  g_lcH);
    cudaGetSymbolAddress((void**)&nodeH, g_nodeH);
    cudaGetSymbolAddress((void**)&leafH, g_leafH);
    cudaGetSymbolAddress((void**)&WtLLG, g_WtLLG);
    cudaGetSymbolAddress((void**)&WtRRG, g_WtRRG);
    cudaGetSymbolAddress((void**)&WtA1, g_WtA1);
    cudaGetSymbolAddress((void**)&WtA2, g_WtA2);
    cudaGetSymbolAddress((void**)&WtS3, g_WtS3);
    cudaGetSymbolAddress((void**)&WtS12, g_WtS12);

    float* out       = (float*)d_out;
    float* out_score = out;
    float* out_node  = out_score + B_ * OT_;
    float* out_ctx   = out_node + B_ * H_;
    float* out_emb   = out_ctx + B_ * H_;

    const int BH = B_ * H_;
    const int TPB = 256;

    cudaFuncSetAttribute(mma_k<0>, cudaFuncAttributeMaxDynamicSharedMemorySize, SMEM_MMA);
    cudaFuncSetAttribute(mma_k<1>, cudaFuncAttributeMaxDynamicSharedMemorySize, SMEM_MMA);
    cudaFuncSetAttribute(mma_k<2>, cudaFuncAttributeMaxDynamicSharedMemorySize, SMEM_MMA);

    // --- fills + conversions + transposes (independent) ---
    {
        int total = 2 * (B_ * 2 * H_) + 2 * BH + B_ * S1_ + B_ * OT_ + OPC_ * H_;
        fill_mega_k<<<(total + TPB - 1) / TPB, TPB>>>(
            gAB, b_l, b_lg, gCD, b_r, b_rg, P1, b_attn, Q1, b_score,
            eng, B_ * S1_, out_score, B_ * OT_, Q2c, OPC_ * H_);
    }
    prep_cur_k<<<(BH + TPB - 1) / TPB, TPB>>>(current, left, curH, lcH);
    {
        size_t total4 = (size_t)B_ * OT_ * (H_ / 4);
        prep_emb_k<<<(unsigned)((total4 + TPB - 1) / TPB), TPB>>>(opc, var, out_emb, opcH, varH);
    }
    {
        int n4 = B_ * S1_ * (H_ / 4);
        cvt_h_k<<<(n4 + TPB - 1) / TPB, TPB>>>(enc, encH, n4);
    }
    transpose5h_k<<<dim3(24, 24, 5), dim3(32, 8)>>>(
        W_l, WtLLG, W_lg, WtLLG + (size_t)H_ * H_,
        W_attn, WtA1, W_attn + (size_t)H_ * H_, WtA2,
        W_score + (size_t)2 * H_ * H_, WtS3);
    transpose3h_k<<<dim3(24, 48, 3), dim3(32, 8)>>>(
        W_r, WtRRG, W_rg, WtRRG + (size_t)H_ * 2 * H_, W_score, WtS12);

    // --- node: two merged gate GEMMs ---
    mma_k<0><<<dim3(6, 2, 6),  512, SMEM_MMA>>>(curH, WtLLG, gAB, nullptr, nullptr,
                                                B_, H_, 4, 2 * H_);
    mma_k<0><<<dim3(6, 2, 12), 512, SMEM_MMA>>>(lcH, WtRRG, gCD, nullptr, nullptr,
                                                B_, 2 * H_, 4, 2 * H_);
    combine_node_k<<<(BH + TPB - 1) / TPB, TPB>>>(has_left, out_node);

    // --- attention ---
    mma_k<0><<<dim3(3, 2, 6), 512, SMEM_MMA>>>(nodeH, WtA1, P1, nullptr, nullptr,
                                               B_, H_, 4, H_);
    mma_k<1><<<dim3(3, (B_ * S1_) / 128, 1), 512, SMEM_MMA>>>(encH, WtA2, eng, P1, v_attn,
                                                              B_ * S1_, H_, 24, 0);
    softmax_context_k<<<B_, 768>>>(smask, encH, out_ctx);

    // --- leaf score ---
    mma_k<0><<<dim3(3, 2, 12), 512, SMEM_MMA>>>(leafH, WtS12, Q1, nullptr, nullptr,
                                                B_, 2 * H_, 4, H_);
    mma_k<0><<<dim3(3, 1, 6),  512, SMEM_MMA>>>(opcH, WtS3, Q2c, nullptr, nullptr,
                                                OPC_, H_, 4, H_);
    mma_k<2><<<dim3(3, (B_ * S2_) / 128, 1), 512, SMEM_MMA>>>(varH, WtS3, out_score, Q1, v_score,
                                                              B_ * S2_, H_, 24, 0);
    finalize_score_k<<<(B_ * OT_ * 32 + TPB - 1) / TPB, TPB>>>(v_score, cmask, out_score);
}